// round 12
// baseline (speedup 1.0000x reference)
#include <cuda_runtime.h>
#include <cuda_bf16.h>

#define NNODES 100000
#define NEDGES 800000
#define ETOT   900000
#define MAXHC  240
#define MAXH   10
#define NEG_SLOPE 0.2f
#define SCAN_BLK 1024
#define NSCAN ((NNODES + SCAN_BLK - 1) / SCAN_BLK)   // 98

// ---------------- scratch (device globals; no allocation allowed) ----------------
__device__ float    g_h   [NNODES * MAXHC];
__device__ float    g_buf0[NNODES * MAXHC];
__device__ float    g_buf1[NNODES * MAXHC];
__device__ float    g_as  [NNODES * MAXH];
__device__ float    g_ad  [NNODES * MAXH];
__device__ float    g_e   [ETOT   * MAXH];      // per-edge exp values (CSR order)
__device__ unsigned g_smaxu[MAXH];              // per-head global max (encoded)
// CSR (built once per launch)
__device__ int g_rowptr [NNODES + 1];
__device__ int g_cnt    [NNODES];
__device__ int g_fill   [NNODES];
__device__ int g_csr_src[ETOT];
__device__ int g_epos   [ETOT];                 // edge id -> csr position
__device__ int g_bsum   [NSCAN];

// ---------------- helpers ----------------
__device__ __forceinline__ unsigned enc_f(float v) {
    unsigned u = __float_as_uint(v);
    return (u & 0x80000000u) ? ~u : (u | 0x80000000u);
}
__device__ __forceinline__ float dec_f(unsigned u) {
    return __uint_as_float((u & 0x80000000u) ? (u ^ 0x80000000u) : ~u);
}

// split fp32 into two tf32 values (3xTF32 trick); x - hi is exact in fp32.
__device__ __forceinline__ void split_tf32(float x, unsigned& hi, unsigned& lo) {
    asm("cvt.rna.tf32.f32 %0, %1;" : "=r"(hi) : "f"(x));
    float r = x - __uint_as_float(hi);
    asm("cvt.rna.tf32.f32 %0, %1;" : "=r"(lo) : "f"(r));
}

__device__ __forceinline__ void mma_tf32(float* d, const unsigned* a, const unsigned* b) {
    asm volatile("mma.sync.aligned.m16n8k8.row.col.f32.tf32.tf32.f32 "
        "{%0,%1,%2,%3}, {%4,%5,%6,%7}, {%8,%9}, {%0,%1,%2,%3};"
        : "+f"(d[0]), "+f"(d[1]), "+f"(d[2]), "+f"(d[3])
        : "r"(a[0]), "r"(a[1]), "r"(a[2]), "r"(a[3]), "r"(b[0]), "r"(b[1]));
}

// ================= CSR build (once per launch) =================
__global__ __launch_bounds__(256) void csr_zero(int* cnt, int* fill, unsigned* smaxu) {
    int i = blockIdx.x * blockDim.x + threadIdx.x;
    if (i < NNODES) { cnt[i] = 0; fill[i] = 0; }
    if (i < MAXH) smaxu[i] = 0u;
}

__global__ __launch_bounds__(256) void csr_hist(const int* __restrict__ ei, int* cnt) {
    int e = blockIdx.x * blockDim.x + threadIdx.x;
    if (e >= ETOT) return;
    int d = (e < NEDGES) ? __ldg(ei + NEDGES + e) : (e - NEDGES);
    atomicAdd(&cnt[d], 1);
}

__global__ __launch_bounds__(SCAN_BLK) void csr_scan1(const int* __restrict__ cnt,
                                                      int* rowptr, int* bsum) {
    __shared__ int sh[SCAN_BLK];
    int gi = blockIdx.x * SCAN_BLK + threadIdx.x;
    int v = (gi < NNODES) ? cnt[gi] : 0;
    sh[threadIdx.x] = v;
    __syncthreads();
    for (int off = 1; off < SCAN_BLK; off <<= 1) {
        int t = (threadIdx.x >= off) ? sh[threadIdx.x - off] : 0;
        __syncthreads();
        sh[threadIdx.x] += t;
        __syncthreads();
    }
    if (gi < NNODES) rowptr[gi] = sh[threadIdx.x] - v;
    if (threadIdx.x == SCAN_BLK - 1) bsum[blockIdx.x] = sh[threadIdx.x];
}

__global__ __launch_bounds__(128) void csr_scan2(int* bsum) {
    __shared__ int sh[128];
    int v = (threadIdx.x < NSCAN) ? bsum[threadIdx.x] : 0;
    sh[threadIdx.x] = v;
    __syncthreads();
    for (int off = 1; off < 128; off <<= 1) {
        int t = (threadIdx.x >= off) ? sh[threadIdx.x - off] : 0;
        __syncthreads();
        sh[threadIdx.x] += t;
        __syncthreads();
    }
    if (threadIdx.x < NSCAN) bsum[threadIdx.x] = sh[threadIdx.x] - v;
}

__global__ __launch_bounds__(SCAN_BLK) void csr_scan3(int* rowptr, const int* __restrict__ bsum) {
    int gi = blockIdx.x * SCAN_BLK + threadIdx.x;
    if (gi < NNODES) rowptr[gi] += bsum[blockIdx.x];
    if (gi == 0) rowptr[NNODES] = ETOT;
}

__global__ __launch_bounds__(256) void csr_fill(const int* __restrict__ ei,
                                                const int* __restrict__ rowptr,
                                                int* fill, int* csr_src, int* epos) {
    int e = blockIdx.x * blockDim.x + threadIdx.x;
    if (e >= ETOT) return;
    int s, d;
    if (e < NEDGES) { s = __ldg(ei + e); d = __ldg(ei + NEDGES + e); }
    else            { s = e - NEDGES; d = s; }
    int pos = rowptr[d] + atomicAdd(&fill[d], 1);
    csr_src[pos] = s;
    epos[e] = pos;
}

// ================= tf32 tensor-core GEMM: out[M,N] = A[M,K] @ W[K,N] =================
// Block 128x64, 8 warps (4m x 2n), warp tile 32x32 (2x4 m16n8 frags).
// BOTH operands are pre-split once per tile into smem tf32 hi/lo planes
// (ldg -> split -> sts, register-prefetched one stage ahead).
// Inner loop is pure lds.u32 + mma. One __syncthreads per k-step.
template<int K, int N>
__global__ __launch_bounds__(256, 3) void gemm_tf32_kernel(
    const float* __restrict__ A, const float* __restrict__ W,
    float* __restrict__ out, int M)
{
    __shared__ unsigned Ah[2][128][12];   // tf32 hi of A [row][k], pad 12 (conflict-free frags)
    __shared__ unsigned Al[2][128][12];   // tf32 lo of A
    __shared__ unsigned Bh[2][8][72];     // tf32 hi of B [k][n], pad 72
    __shared__ unsigned Bl[2][8][72];     // tf32 lo of B

    const int tid  = threadIdx.x;
    const int lane = tid & 31;
    const int warp = tid >> 5;
    const int wm   = warp & 3;
    const int wn   = warp >> 2;
    const int row0 = blockIdx.y * 128;
    const int col0 = blockIdx.x * 64;

    float acc[2][4][4];
#pragma unroll
    for (int mt = 0; mt < 2; mt++)
#pragma unroll
        for (int nt = 0; nt < 4; nt++)
#pragma unroll
            for (int i = 0; i < 4; i++) acc[mt][nt][i] = 0.f;

    // ---- A loader: thread -> 4 floats of one row ----
    const int arow = tid >> 1;
    const int ah4  = (tid & 1) * 4;
    const int gr   = row0 + arow;
    const float* a_src = A + (long)(gr < M ? gr : 0) * K + ah4;
    const bool a_ok = (gr < M);

    auto ldg_a = [&](int k0) -> float4 {
        return a_ok ? *(const float4*)(a_src + k0) : make_float4(0.f, 0.f, 0.f, 0.f);
    };
    auto store_a = [&](int buf, float4 v) {
        unsigned h0, l0, h1, l1, h2, l2, h3, l3;
        split_tf32(v.x, h0, l0); split_tf32(v.y, h1, l1);
        split_tf32(v.z, h2, l2); split_tf32(v.w, h3, l3);
        unsigned* ph = &Ah[buf][arow][ah4];
        unsigned* pl = &Al[buf][arow][ah4];
        ph[0] = h0; ph[1] = h1; ph[2] = h2; ph[3] = h3;
        pl[0] = l0; pl[1] = l1; pl[2] = l2; pl[3] = l3;
    };

    // ---- B loader (tid<128 active): thread -> 4 floats of one k-row ----
    const int bk   = (tid & 127) >> 4;      // 0..7
    const int bnc  = tid & 15;              // 0..15 -> 4 floats each
    const int gcol = col0 + bnc * 4;
    const int rem  = N - gcol;

    auto ldg_b = [&](int k0) -> float4 {
        float4 v = make_float4(0.f, 0.f, 0.f, 0.f);
        if (tid < 128 && rem > 0) {
            const float* p = W + (long)(k0 + bk) * N + gcol;
            if (rem >= 4) v = *(const float4*)p;
            else { v.x = p[0]; if (rem > 1) v.y = p[1]; if (rem > 2) v.z = p[2]; }
        }
        return v;
    };
    auto store_b = [&](int buf, float4 v) {
        if (tid < 128) {
            unsigned h0, l0, h1, l1, h2, l2, h3, l3;
            split_tf32(v.x, h0, l0); split_tf32(v.y, h1, l1);
            split_tf32(v.z, h2, l2); split_tf32(v.w, h3, l3);
            unsigned* ph = &Bh[buf][bk][bnc * 4];
            unsigned* pl = &Bl[buf][bk][bnc * 4];
            ph[0] = h0; ph[1] = h1; ph[2] = h2; ph[3] = h3;
            pl[0] = l0; pl[1] = l1; pl[2] = l2; pl[3] = l3;
        }
    };

    constexpr int NK = K / 8;

    // ---- prologue: stage 0 ----
    store_a(0, ldg_a(0));
    store_b(0, ldg_b(0));
    __syncthreads();

#pragma unroll 1
    for (int s = 0; s < NK; s++) {
        const bool more = (s + 1 < NK);
        float4 an, bn;
        if (more) {
            const int k0n = (s + 1) * 8;
            an = ldg_a(k0n);               // ldg latency hidden by MMA phase
            bn = ldg_b(k0n);
        }

        const int buf = s & 1;
        // A fragments: pure lds.u32 from pre-split planes
        unsigned ahf[2][4], alf[2][4];
#pragma unroll
        for (int mt = 0; mt < 2; mt++) {
            const int r = wm * 32 + mt * 16 + (lane >> 2);
            const int k = lane & 3;
            const unsigned* ph = &Ah[buf][r][k];
            const unsigned* pl = &Al[buf][r][k];
            ahf[mt][0] = ph[0];   alf[mt][0] = pl[0];     // (r,   k)
            ahf[mt][1] = ph[96];  alf[mt][1] = pl[96];    // (r+8, k)   8*12
            ahf[mt][2] = ph[4];   alf[mt][2] = pl[4];     // (r,   k+4)
            ahf[mt][3] = ph[100]; alf[mt][3] = pl[100];   // (r+8, k+4)
        }
        // B fragments + 3xTF32 mma
#pragma unroll
        for (int nt = 0; nt < 4; nt++) {
            const int ci = wn * 32 + nt * 8 + (lane >> 2);
            const int ki = lane & 3;
            unsigned bh[2], bl[2];
            bh[0] = Bh[buf][ki][ci];     bh[1] = Bh[buf][ki + 4][ci];
            bl[0] = Bl[buf][ki][ci];     bl[1] = Bl[buf][ki + 4][ci];
#pragma unroll
            for (int mt = 0; mt < 2; mt++) {
                mma_tf32(acc[mt][nt], ahf[mt], bh);
                mma_tf32(acc[mt][nt], ahf[mt], bl);
                mma_tf32(acc[mt][nt], alf[mt], bh);
            }
        }

        if (more) {
            store_a((s + 1) & 1, an);      // alternate buffer — safe pre-sync
            store_b((s + 1) & 1, bn);
            __syncthreads();
        }
    }

    // ---- epilogue: guarded float2 stores ----
#pragma unroll
    for (int mt = 0; mt < 2; mt++) {
#pragma unroll
        for (int nt = 0; nt < 4; nt++) {
            int r = row0 + wm * 32 + mt * 16 + (lane >> 2);
            int c = col0 + wn * 32 + nt * 8 + (lane & 3) * 2;
            if (c + 1 < N) {
                if (r < M)
                    *(float2*)(out + (long)r * N + c) =
                        make_float2(acc[mt][nt][0], acc[mt][nt][1]);
                if (r + 8 < M)
                    *(float2*)(out + (long)(r + 8) * N + c) =
                        make_float2(acc[mt][nt][2], acc[mt][nt][3]);
            }
        }
    }
}

// ================= alpha + per-head global max =================
template<int H, int C>
__global__ __launch_bounds__(256) void alpha_kernel(
    const float* __restrict__ h, const float* __restrict__ a_s,
    const float* __restrict__ a_d, float* __restrict__ alpha_s,
    float* __restrict__ alpha_d, unsigned* __restrict__ smaxu)
{
    __shared__ unsigned s_max[H];
    if (threadIdx.x < H) s_max[threadIdx.x] = 0u;
    __syncthreads();

    int idx = blockIdx.x * blockDim.x + threadIdx.x;
    if (idx < NNODES * H) {
        int node = idx / H;
        int hh = idx - node * H;
        const float4* hp  = (const float4*)(h + (long)node * H * C + hh * C);
        const float4* asp = (const float4*)(a_s + hh * C);
        const float4* adp = (const float4*)(a_d + hh * C);
        float ss = 0.f, sd = 0.f;
#pragma unroll
        for (int c = 0; c < C / 4; c++) {
            float4 v = hp[c];
            float4 s4 = __ldg(asp + c);
            float4 d4 = __ldg(adp + c);
            ss += v.x * s4.x + v.y * s4.y + v.z * s4.z + v.w * s4.w;
            sd += v.x * d4.x + v.y * d4.y + v.z * d4.z + v.w * d4.w;
        }
        alpha_s[idx] = ss;
        alpha_d[idx] = sd;
        atomicMax(&s_max[hh], enc_f(ss));
    }
    __syncthreads();
    if (threadIdx.x < H)
        atomicMax(&smaxu[threadIdx.x], s_max[threadIdx.x]);
}

// ================= fused edge pass: exp(e - m_ub), CSR-ordered store =================
template<int H>
__global__ __launch_bounds__(256) void edge_fused(
    const int* __restrict__ ei, const int* __restrict__ epos,
    const float* __restrict__ as, const float* __restrict__ ad,
    const unsigned* __restrict__ smaxu, float* __restrict__ ebuf)
{
    int idx = blockIdx.x * blockDim.x + threadIdx.x;
    if (idx >= ETOT * H) return;
    int e  = idx / H;
    int hh = idx - e * H;
    int s, d;
    if (e < NEDGES) { s = __ldg(ei + e); d = __ldg(ei + NEDGES + e); }
    else            { s = e - NEDGES; d = s; }
    float asv = __ldg(as + s * H + hh);
    float adv = __ldg(ad + d * H + hh);
    float ev = asv + adv;
    ev = (ev > 0.f) ? ev : NEG_SLOPE * ev;
    float mb = dec_f(__ldg(smaxu + hh)) + adv;
    mb = (mb > 0.f) ? mb : NEG_SLOPE * mb;
    float ex = __expf(ev - mb);
    int pos = __ldg(epos + e);
    ebuf[(long)pos * H + hh] = ex;      // scattered write (fire-and-forget)
}

// ================= CSR gather + bias + ReLU epilogue =================
template<int H, int C>
__global__ __launch_bounds__(256) void node_gather(
    const int* __restrict__ rowptr, const int* __restrict__ csr_src,
    const float* __restrict__ ex, const float* __restrict__ h,
    const float* __restrict__ bias, float* __restrict__ out,
    unsigned* __restrict__ smaxu)
{
    constexpr int NCH = H * C / 4;
    constexpr int HC  = H * C;
    long idx = (long)blockIdx.x * blockDim.x + threadIdx.x;
    if (idx < MAXH) smaxu[idx] = 0u;
    if (idx >= (long)NNODES * NCH) return;
    int n = (int)(idx / NCH);
    int q = (int)(idx - (long)n * NCH);
    int head = q / (C / 4);

    int beg = __ldg(rowptr + n);
    int end = __ldg(rowptr + n + 1);
    float4 acc = make_float4(0.f, 0.f, 0.f, 0.f);
    float zs = 0.f;
    int j = beg;
    for (; j + 1 < end; j += 2) {
        int s0 = __ldg(csr_src + j);
        int s1 = __ldg(csr_src + j + 1);
        float a0 = __ldg(ex + (long)j * H + head);
        float a1 = __ldg(ex + (long)(j + 1) * H + head);
        float4 h0 = *(const float4*)(h + (long)s0 * HC + q * 4);
        float4 h1 = *(const float4*)(h + (long)s1 * HC + q * 4);
        acc.x += h0.x * a0; acc.y += h0.y * a0;
        acc.z += h0.z * a0; acc.w += h0.w * a0;
        acc.x += h1.x * a1; acc.y += h1.y * a1;
        acc.z += h1.z * a1; acc.w += h1.w * a1;
        zs += a0 + a1;
    }
    if (j < end) {
        int s0 = __ldg(csr_src + j);
        float a0 = __ldg(ex + (long)j * H + head);
        float4 h0 = *(const float4*)(h + (long)s0 * HC + q * 4);
        acc.x += h0.x * a0; acc.y += h0.y * a0;
        acc.z += h0.z * a0; acc.w += h0.w * a0;
        zs += a0;
    }
    float rzv = __frcp_rn(zs);
    const float4 bv = __ldg((const float4*)(bias + q * 4));
    *(float4*)(out + (long)n * HC + q * 4) =
        make_float4(fmaxf(acc.x * rzv + bv.x, 0.f),
                    fmaxf(acc.y * rzv + bv.y, 0.f),
                    fmaxf(acc.z * rzv + bv.z, 0.f),
                    fmaxf(acc.w * rzv + bv.w, 0.f));
}

// ================= per-layer templated driver (minus GEMM) =================
template<int H, int C>
static void run_layer_rest(const float* a_s, const float* a_d, const float* bias,
                           const int* ei, const int* epos,
                           float* h, float* as, float* ad,
                           float* ebuf, unsigned* smaxu,
                           const int* rowptr, const int* csr_src,
                           float* outb)
{
    constexpr int HC = H * C;
    {
        int n = NNODES * H;
        alpha_kernel<H, C><<<(n + 255) / 256, 256>>>(h, a_s, a_d, as, ad, smaxu);
    }
    {
        int n = ETOT * H;
        edge_fused<H><<<(n + 255) / 256, 256>>>(ei, epos, as, ad, smaxu, ebuf);
    }
    {
        long total = (long)NNODES * (HC / 4);
        int blocks = (int)((total + 255) / 256);
        node_gather<H, C><<<blocks, 256>>>(rowptr, csr_src, ebuf, h, bias, outb, smaxu);
    }
}

template<int K, int N>
static void launch_gemm(const float* A, const float* W, float* out) {
    dim3 grid((N + 63) / 64, (NNODES + 127) / 128);
    gemm_tf32_kernel<K, N><<<grid, 256>>>(A, W, out, NNODES);
}

// ================= host orchestration =================
extern "C" void kernel_launch(void* const* d_in, const int* in_sizes, int n_in,
                              void* d_out, int out_size)
{
    const float* x  = (const float*)d_in[0];
    const int*   ei = (const int*)d_in[1];

    float *h, *buf0, *buf1, *as, *ad, *ebuf;
    unsigned* smaxu;
    int *rowptr, *cnt, *fill, *csr_src, *epos, *bsum;
    {
        void* p;
        cudaGetSymbolAddress(&p, g_h);       h       = (float*)p;
        cudaGetSymbolAddress(&p, g_buf0);    buf0    = (float*)p;
        cudaGetSymbolAddress(&p, g_buf1);    buf1    = (float*)p;
        cudaGetSymbolAddress(&p, g_as);      as      = (float*)p;
        cudaGetSymbolAddress(&p, g_ad);      ad      = (float*)p;
        cudaGetSymbolAddress(&p, g_e);       ebuf    = (float*)p;
        cudaGetSymbolAddress(&p, g_smaxu);   smaxu   = (unsigned*)p;
        cudaGetSymbolAddress(&p, g_rowptr);  rowptr  = (int*)p;
        cudaGetSymbolAddress(&p, g_cnt);     cnt     = (int*)p;
        cudaGetSymbolAddress(&p, g_fill);    fill    = (int*)p;
        cudaGetSymbolAddress(&p, g_csr_src); csr_src = (int*)p;
        cudaGetSymbolAddress(&p, g_epos);    epos    = (int*)p;
        cudaGetSymbolAddress(&p, g_bsum);    bsum    = (int*)p;
    }

    const float* W[5]; const float* B[5]; const float* AS[5]; const float* AD[5];
    for (int i = 0; i < 5; i++) {
        W[i]  = (const float*)d_in[3 + 4 * i];
        B[i]  = (const float*)d_in[4 + 4 * i];
        AS[i] = (const float*)d_in[5 + 4 * i];
        AD[i] = (const float*)d_in[6 + 4 * i];
    }

    // ---- CSR build interleaved with layer-0 GEMM (independent) ----
    csr_zero<<<(NNODES + 255) / 256, 256>>>(cnt, fill, smaxu);          // #1
    csr_hist<<<(ETOT + 255) / 256, 256>>>(ei, cnt);                     // #2
    csr_scan1<<<NSCAN, SCAN_BLK>>>(cnt, rowptr, bsum);                  // #3
    launch_gemm< 32, 240>(x, W[0], h);                                  // #4 (profiled)
    csr_scan2<<<1, 128>>>(bsum);                                        // #5
    csr_scan3<<<NSCAN, SCAN_BLK>>>(rowptr, bsum);                       // #6
    csr_fill<<<(ETOT + 255) / 256, 256>>>(ei, rowptr, fill, csr_src, epos); // #7

    // ---- layer 0 rest (gather applies bias B[0] + relu -> buf0) ----
    run_layer_rest<10, 24>(AS[0], AD[0], B[0], ei, epos, h, as, ad, ebuf, smaxu, rowptr, csr_src, buf0);

    // ---- layers 1-4 ----
    launch_gemm<240, 120>(buf0, W[1], h);
    run_layer_rest< 5, 24>(AS[1], AD[1], B[1], ei, epos, h, as, ad, ebuf, smaxu, rowptr, csr_src, buf1);

    launch_gemm<120,  48>(buf1, W[2], h);
    run_layer_rest< 2, 24>(AS[2], AD[2], B[2], ei, epos, h, as, ad, ebuf, smaxu, rowptr, csr_src, buf0);

    launch_gemm< 48,  24>(buf0, W[3], h);
    run_layer_rest< 1, 24>(AS[3], AD[3], B[3], ei, epos, h, as, ad, ebuf, smaxu, rowptr, csr_src, buf1);

    launch_gemm< 24,  12>(buf1, W[4], h);
    run_layer_rest< 1, 12>(AS[4], AD[4], B[4], ei, epos, h, as, ad, ebuf, smaxu, rowptr, csr_src, (float*)d_out);
}

// round 13
// speedup vs baseline: 1.0698x; 1.0698x over previous
#include <cuda_runtime.h>
#include <cuda_bf16.h>
#include <cuda_fp16.h>

#define NNODES 100000
#define NEDGES 800000
#define ETOT   900000
#define MAXHC  240
#define MAXH   10
#define NEG_SLOPE 0.2f
#define SCAN_BLK 1024
#define NSCAN ((NNODES + SCAN_BLK - 1) / SCAN_BLK)   // 98

// ---------------- scratch (device globals; no allocation allowed) ----------------
__device__ float    g_h   [NNODES * MAXHC];     // fp32 h (for alpha)
__device__ __half   g_h2  [NNODES * MAXHC];     // fp16 h (for gather)
__device__ float    g_buf0[NNODES * MAXHC];
__device__ float    g_buf1[NNODES * MAXHC];
__device__ float    g_as  [NNODES * MAXH];
__device__ float    g_ad  [NNODES * MAXH];
__device__ float    g_e   [ETOT   * MAXH];      // per-edge exp values (CSR order)
__device__ unsigned g_smaxu[MAXH];              // per-head global max (encoded)
// CSR (built once per launch)
__device__ int g_rowptr [NNODES + 1];
__device__ int g_cnt    [NNODES];
__device__ int g_fill   [NNODES];
__device__ int g_csr_src[ETOT];
__device__ int g_epos   [ETOT];                 // edge id -> csr position
__device__ int g_bsum   [NSCAN];

// ---------------- helpers ----------------
__device__ __forceinline__ unsigned enc_f(float v) {
    unsigned u = __float_as_uint(v);
    return (u & 0x80000000u) ? ~u : (u | 0x80000000u);
}
__device__ __forceinline__ float dec_f(unsigned u) {
    return __uint_as_float((u & 0x80000000u) ? (u ^ 0x80000000u) : ~u);
}

// split fp32 into two tf32 values (3xTF32 trick); x - hi is exact in fp32.
__device__ __forceinline__ void split_tf32(float x, unsigned& hi, unsigned& lo) {
    asm("cvt.rna.tf32.f32 %0, %1;" : "=r"(hi) : "f"(x));
    float r = x - __uint_as_float(hi);
    asm("cvt.rna.tf32.f32 %0, %1;" : "=r"(lo) : "f"(r));
}

__device__ __forceinline__ void mma_tf32(float* d, const unsigned* a, const unsigned* b) {
    asm volatile("mma.sync.aligned.m16n8k8.row.col.f32.tf32.tf32.f32 "
        "{%0,%1,%2,%3}, {%4,%5,%6,%7}, {%8,%9}, {%0,%1,%2,%3};"
        : "+f"(d[0]), "+f"(d[1]), "+f"(d[2]), "+f"(d[3])
        : "r"(a[0]), "r"(a[1]), "r"(a[2]), "r"(a[3]), "r"(b[0]), "r"(b[1]));
}

#define CP_ASYNC16(dst, src, sz) \
    asm volatile("cp.async.ca.shared.global [%0], [%1], 16, %2;" \
                 :: "r"(dst), "l"(src), "r"(sz) : "memory")
#define CP_COMMIT()  asm volatile("cp.async.commit_group;" ::: "memory")
#define CP_WAIT0()   asm volatile("cp.async.wait_group 0;" ::: "memory")

// ================= CSR build (once per launch) =================
__global__ __launch_bounds__(256) void csr_zero(int* cnt, int* fill, unsigned* smaxu) {
    int i = blockIdx.x * blockDim.x + threadIdx.x;
    if (i < NNODES) { cnt[i] = 0; fill[i] = 0; }
    if (i < MAXH) smaxu[i] = 0u;
}

__global__ __launch_bounds__(256) void csr_hist(const int* __restrict__ ei, int* cnt) {
    int e = blockIdx.x * blockDim.x + threadIdx.x;
    if (e >= ETOT) return;
    int d = (e < NEDGES) ? __ldg(ei + NEDGES + e) : (e - NEDGES);
    atomicAdd(&cnt[d], 1);
}

__global__ __launch_bounds__(SCAN_BLK) void csr_scan1(const int* __restrict__ cnt,
                                                      int* rowptr, int* bsum) {
    __shared__ int sh[SCAN_BLK];
    int gi = blockIdx.x * SCAN_BLK + threadIdx.x;
    int v = (gi < NNODES) ? cnt[gi] : 0;
    sh[threadIdx.x] = v;
    __syncthreads();
    for (int off = 1; off < SCAN_BLK; off <<= 1) {
        int t = (threadIdx.x >= off) ? sh[threadIdx.x - off] : 0;
        __syncthreads();
        sh[threadIdx.x] += t;
        __syncthreads();
    }
    if (gi < NNODES) rowptr[gi] = sh[threadIdx.x] - v;
    if (threadIdx.x == SCAN_BLK - 1) bsum[blockIdx.x] = sh[threadIdx.x];
}

__global__ __launch_bounds__(128) void csr_scan2(int* bsum) {
    __shared__ int sh[128];
    int v = (threadIdx.x < NSCAN) ? bsum[threadIdx.x] : 0;
    sh[threadIdx.x] = v;
    __syncthreads();
    for (int off = 1; off < 128; off <<= 1) {
        int t = (threadIdx.x >= off) ? sh[threadIdx.x - off] : 0;
        __syncthreads();
        sh[threadIdx.x] += t;
        __syncthreads();
    }
    if (threadIdx.x < NSCAN) bsum[threadIdx.x] = sh[threadIdx.x] - v;
}

__global__ __launch_bounds__(SCAN_BLK) void csr_scan3(int* rowptr, const int* __restrict__ bsum) {
    int gi = blockIdx.x * SCAN_BLK + threadIdx.x;
    if (gi < NNODES) rowptr[gi] += bsum[blockIdx.x];
    if (gi == 0) rowptr[NNODES] = ETOT;
}

__global__ __launch_bounds__(256) void csr_fill(const int* __restrict__ ei,
                                                const int* __restrict__ rowptr,
                                                int* fill, int* csr_src, int* epos) {
    int e = blockIdx.x * blockDim.x + threadIdx.x;
    if (e >= ETOT) return;
    int s, d;
    if (e < NEDGES) { s = __ldg(ei + e); d = __ldg(ei + NEDGES + e); }
    else            { s = e - NEDGES; d = s; }
    int pos = rowptr[d] + atomicAdd(&fill[d], 1);
    csr_src[pos] = s;
    epos[e] = pos;
}

// ================= tf32 tensor-core GEMM (round-11 layout) =================
// Block 128x64, 8 warps (4m x 2n), warp tile 32x32 (2x4 m16n8 frags).
// A: cp.async double-buffered raw, per-fragment 3xTF32 split.
// B: register-prefetched, pre-split once per tile into smem hi/lo planes.
// Epilogue writes BOTH fp32 h (for alpha) and fp16 h2 (for gather).
template<int K, int N>
__global__ __launch_bounds__(256, 3) void gemm_tf32_kernel(
    const float* __restrict__ A, const float* __restrict__ W,
    float* __restrict__ out, __half* __restrict__ out2, int M)
{
    __shared__ float    As[2][128][12];
    __shared__ unsigned Bh[2][8][72];
    __shared__ unsigned Bl[2][8][72];

    const int tid  = threadIdx.x;
    const int lane = tid & 31;
    const int warp = tid >> 5;
    const int wm   = warp & 3;
    const int wn   = warp >> 2;
    const int row0 = blockIdx.y * 128;
    const int col0 = blockIdx.x * 64;

    float acc[2][4][4];
#pragma unroll
    for (int mt = 0; mt < 2; mt++)
#pragma unroll
        for (int nt = 0; nt < 4; nt++)
#pragma unroll
            for (int i = 0; i < 4; i++) acc[mt][nt][i] = 0.f;

    const int arow = tid >> 1;
    const int ah4  = (tid & 1) * 4;
    const int gr   = row0 + arow;
    const unsigned a_sz = (gr < M) ? 16u : 0u;
    const float* a_src = A + (long)(gr < M ? gr : 0) * K + ah4;
    unsigned a_dst[2];
    a_dst[0] = (unsigned)__cvta_generic_to_shared(&As[0][arow][ah4]);
    a_dst[1] = (unsigned)__cvta_generic_to_shared(&As[1][arow][ah4]);

    const int bk   = (tid & 127) >> 4;
    const int bnc  = tid & 15;
    const int gcol = col0 + bnc * 4;
    const int rem  = N - gcol;

    auto ldg_b = [&](int k0) -> float4 {
        float4 v = make_float4(0.f, 0.f, 0.f, 0.f);
        if (tid < 128 && rem > 0) {
            const float* p = W + (long)(k0 + bk) * N + gcol;
            if (rem >= 4) v = *(const float4*)p;
            else { v.x = p[0]; if (rem > 1) v.y = p[1]; if (rem > 2) v.z = p[2]; }
        }
        return v;
    };
    auto store_b = [&](int buf, float4 v) {
        if (tid < 128) {
            unsigned h0, l0, h1, l1, h2, l2, h3, l3;
            split_tf32(v.x, h0, l0); split_tf32(v.y, h1, l1);
            split_tf32(v.z, h2, l2); split_tf32(v.w, h3, l3);
            unsigned* ph = &Bh[buf][bk][bnc * 4];
            unsigned* pl = &Bl[buf][bk][bnc * 4];
            ph[0] = h0; ph[1] = h1; ph[2] = h2; ph[3] = h3;
            pl[0] = l0; pl[1] = l1; pl[2] = l2; pl[3] = l3;
        }
    };

    constexpr int NK = K / 8;

    CP_ASYNC16(a_dst[0], a_src, a_sz);
    CP_COMMIT();
    store_b(0, ldg_b(0));
    CP_WAIT0();
    __syncthreads();

#pragma unroll 1
    for (int s = 0; s < NK; s++) {
        const bool more = (s + 1 < NK);
        float4 bn;
        if (more) {
            const int k0n = (s + 1) * 8;
            CP_ASYNC16(a_dst[(s + 1) & 1], a_src + k0n, a_sz);
            CP_COMMIT();
            bn = ldg_b(k0n);
        }

        const int buf = s & 1;
        unsigned ahf[2][4], alf[2][4];
#pragma unroll
        for (int mt = 0; mt < 2; mt++) {
            const float* ap = &As[buf][wm * 32 + mt * 16 + (lane >> 2)][lane & 3];
            split_tf32(ap[0],   ahf[mt][0], alf[mt][0]);
            split_tf32(ap[96],  ahf[mt][1], alf[mt][1]);
            split_tf32(ap[4],   ahf[mt][2], alf[mt][2]);
            split_tf32(ap[100], ahf[mt][3], alf[mt][3]);
        }
#pragma unroll
        for (int nt = 0; nt < 4; nt++) {
            const int ci = wn * 32 + nt * 8 + (lane >> 2);
            const int ki = lane & 3;
            unsigned bh[2], bl[2];
            bh[0] = Bh[buf][ki][ci];     bh[1] = Bh[buf][ki + 4][ci];
            bl[0] = Bl[buf][ki][ci];     bl[1] = Bl[buf][ki + 4][ci];
#pragma unroll
            for (int mt = 0; mt < 2; mt++) {
                mma_tf32(acc[mt][nt], ahf[mt], bh);
                mma_tf32(acc[mt][nt], ahf[mt], bl);
                mma_tf32(acc[mt][nt], alf[mt], bh);
            }
        }

        if (more) {
            store_b((s + 1) & 1, bn);
            CP_WAIT0();
            __syncthreads();
        }
    }

    // ---- epilogue: fp32 + fp16 guarded stores ----
#pragma unroll
    for (int mt = 0; mt < 2; mt++) {
#pragma unroll
        for (int nt = 0; nt < 4; nt++) {
            int r = row0 + wm * 32 + mt * 16 + (lane >> 2);
            int c = col0 + wn * 32 + nt * 8 + (lane & 3) * 2;
            if (c + 1 < N) {
                if (r < M) {
                    *(float2*)(out + (long)r * N + c) =
                        make_float2(acc[mt][nt][0], acc[mt][nt][1]);
                    *(__half2*)(out2 + (long)r * N + c) =
                        __floats2half2_rn(acc[mt][nt][0], acc[mt][nt][1]);
                }
                if (r + 8 < M) {
                    *(float2*)(out + (long)(r + 8) * N + c) =
                        make_float2(acc[mt][nt][2], acc[mt][nt][3]);
                    *(__half2*)(out2 + (long)(r + 8) * N + c) =
                        __floats2half2_rn(acc[mt][nt][2], acc[mt][nt][3]);
                }
            }
        }
    }
}

// ================= alpha + per-head global max (fp32 h) =================
template<int H, int C>
__global__ __launch_bounds__(256) void alpha_kernel(
    const float* __restrict__ h, const float* __restrict__ a_s,
    const float* __restrict__ a_d, float* __restrict__ alpha_s,
    float* __restrict__ alpha_d, unsigned* __restrict__ smaxu)
{
    __shared__ unsigned s_max[H];
    if (threadIdx.x < H) s_max[threadIdx.x] = 0u;
    __syncthreads();

    int idx = blockIdx.x * blockDim.x + threadIdx.x;
    if (idx < NNODES * H) {
        int node = idx / H;
        int hh = idx - node * H;
        const float4* hp  = (const float4*)(h + (long)node * H * C + hh * C);
        const float4* asp = (const float4*)(a_s + hh * C);
        const float4* adp = (const float4*)(a_d + hh * C);
        float ss = 0.f, sd = 0.f;
#pragma unroll
        for (int c = 0; c < C / 4; c++) {
            float4 v = hp[c];
            float4 s4 = __ldg(asp + c);
            float4 d4 = __ldg(adp + c);
            ss += v.x * s4.x + v.y * s4.y + v.z * s4.z + v.w * s4.w;
            sd += v.x * d4.x + v.y * d4.y + v.z * d4.z + v.w * d4.w;
        }
        alpha_s[idx] = ss;
        alpha_d[idx] = sd;
        atomicMax(&s_max[hh], enc_f(ss));
    }
    __syncthreads();
    if (threadIdx.x < H)
        atomicMax(&smaxu[threadIdx.x], s_max[threadIdx.x]);
}

// ================= fused edge pass: exp(e - m_ub), CSR-ordered store =================
template<int H>
__global__ __launch_bounds__(256) void edge_fused(
    const int* __restrict__ ei, const int* __restrict__ epos,
    const float* __restrict__ as, const float* __restrict__ ad,
    const unsigned* __restrict__ smaxu, float* __restrict__ ebuf)
{
    int idx = blockIdx.x * blockDim.x + threadIdx.x;
    if (idx >= ETOT * H) return;
    int e  = idx / H;
    int hh = idx - e * H;
    int s, d;
    if (e < NEDGES) { s = __ldg(ei + e); d = __ldg(ei + NEDGES + e); }
    else            { s = e - NEDGES; d = s; }
    float asv = __ldg(as + s * H + hh);
    float adv = __ldg(ad + d * H + hh);
    float ev = asv + adv;
    ev = (ev > 0.f) ? ev : NEG_SLOPE * ev;
    float mb = dec_f(__ldg(smaxu + hh)) + adv;
    mb = (mb > 0.f) ? mb : NEG_SLOPE * mb;
    float ex = __expf(ev - mb);
    int pos = __ldg(epos + e);
    ebuf[(long)pos * H + hh] = ex;      // scattered write (fire-and-forget)
}

// ================= CSR gather (fp16 h) + bias + ReLU epilogue =================
template<int H, int C>
__global__ __launch_bounds__(256) void node_gather(
    const int* __restrict__ rowptr, const int* __restrict__ csr_src,
    const float* __restrict__ ex, const __half* __restrict__ h2,
    const float* __restrict__ bias, float* __restrict__ out,
    unsigned* __restrict__ smaxu)
{
    constexpr int NCH = H * C / 4;
    constexpr int HC  = H * C;
    long idx = (long)blockIdx.x * blockDim.x + threadIdx.x;
    if (idx < MAXH) smaxu[idx] = 0u;
    if (idx >= (long)NNODES * NCH) return;
    int n = (int)(idx / NCH);
    int q = (int)(idx - (long)n * NCH);
    int head = q / (C / 4);

    int beg = __ldg(rowptr + n);
    int end = __ldg(rowptr + n + 1);
    float4 acc = make_float4(0.f, 0.f, 0.f, 0.f);
    float zs = 0.f;

    auto accum = [&](int j) {
        int s0 = __ldg(csr_src + j);
        float a0 = __ldg(ex + (long)j * H + head);
        uint2 raw = *(const uint2*)(h2 + (long)s0 * HC + q * 4);
        float2 f0 = __half22float2(*reinterpret_cast<__half2*>(&raw.x));
        float2 f1 = __half22float2(*reinterpret_cast<__half2*>(&raw.y));
        acc.x += f0.x * a0; acc.y += f0.y * a0;
        acc.z += f1.x * a0; acc.w += f1.y * a0;
        zs += a0;
    };

    int j = beg;
    for (; j + 1 < end; j += 2) { accum(j); accum(j + 1); }
    if (j < end) accum(j);

    float rzv = __frcp_rn(zs);
    const float4 bv = __ldg((const float4*)(bias + q * 4));
    *(float4*)(out + (long)n * HC + q * 4) =
        make_float4(fmaxf(acc.x * rzv + bv.x, 0.f),
                    fmaxf(acc.y * rzv + bv.y, 0.f),
                    fmaxf(acc.z * rzv + bv.z, 0.f),
                    fmaxf(acc.w * rzv + bv.w, 0.f));
}

// ================= per-layer templated driver (minus GEMM) =================
template<int H, int C>
static void run_layer_rest(const float* a_s, const float* a_d, const float* bias,
                           const int* ei, const int* epos,
                           float* h, const __half* h2, float* as, float* ad,
                           float* ebuf, unsigned* smaxu,
                           const int* rowptr, const int* csr_src,
                           float* outb)
{
    constexpr int HC = H * C;
    {
        int n = NNODES * H;
        alpha_kernel<H, C><<<(n + 255) / 256, 256>>>(h, a_s, a_d, as, ad, smaxu);
    }
    {
        int n = ETOT * H;
        edge_fused<H><<<(n + 255) / 256, 256>>>(ei, epos, as, ad, smaxu, ebuf);
    }
    {
        long total = (long)NNODES * (HC / 4);
        int blocks = (int)((total + 255) / 256);
        node_gather<H, C><<<blocks, 256>>>(rowptr, csr_src, ebuf, h2, bias, outb, smaxu);
    }
}

template<int K, int N>
static void launch_gemm(const float* A, const float* W, float* out, __half* out2) {
    dim3 grid((N + 63) / 64, (NNODES + 127) / 128);
    gemm_tf32_kernel<K, N><<<grid, 256>>>(A, W, out, out2, NNODES);
}

// ================= host orchestration =================
extern "C" void kernel_launch(void* const* d_in, const int* in_sizes, int n_in,
                              void* d_out, int out_size)
{
    const float* x  = (const float*)d_in[0];
    const int*   ei = (const int*)d_in[1];

    float *h, *buf0, *buf1, *as, *ad, *ebuf;
    __half* h2;
    unsigned* smaxu;
    int *rowptr, *cnt, *fill, *csr_src, *epos, *bsum;
    {
        void* p;
        cudaGetSymbolAddress(&p, g_h);       h       = (float*)p;
        cudaGetSymbolAddress(&p, g_h2);      h2      = (__half*)p;
        cudaGetSymbolAddress(&p, g_buf0);    buf0    = (float*)p;
        cudaGetSymbolAddress(&p, g_buf1);    buf1    = (float*)p;
        cudaGetSymbolAddress(&p, g_as);      as      = (float*)p;
        cudaGetSymbolAddress(&p, g_ad);      ad      = (float*)p;
        cudaGetSymbolAddress(&p, g_e);       ebuf    = (float*)p;
        cudaGetSymbolAddress(&p, g_smaxu);   smaxu   = (unsigned*)p;
        cudaGetSymbolAddress(&p, g_rowptr);  rowptr  = (int*)p;
        cudaGetSymbolAddress(&p, g_cnt);     cnt     = (int*)p;
        cudaGetSymbolAddress(&p, g_fill);    fill    = (int*)p;
        cudaGetSymbolAddress(&p, g_csr_src); csr_src = (int*)p;
        cudaGetSymbolAddress(&p, g_epos);    epos    = (int*)p;
        cudaGetSymbolAddress(&p, g_bsum);    bsum    = (int*)p;
    }

    const float* W[5]; const float* B[5]; const float* AS[5]; const float* AD[5];
    for (int i = 0; i < 5; i++) {
        W[i]  = (const float*)d_in[3 + 4 * i];
        B[i]  = (const float*)d_in[4 + 4 * i];
        AS[i] = (const float*)d_in[5 + 4 * i];
        AD[i] = (const float*)d_in[6 + 4 * i];
    }

    // ---- CSR build interleaved with layer-0 GEMM (independent) ----
    csr_zero<<<(NNODES + 255) / 256, 256>>>(cnt, fill, smaxu);          // #1
    csr_hist<<<(ETOT + 255) / 256, 256>>>(ei, cnt);                     // #2
    csr_scan1<<<NSCAN, SCAN_BLK>>>(cnt, rowptr, bsum);                  // #3
    launch_gemm< 32, 240>(x, W[0], h, h2);                              // #4 (profiled)
    csr_scan2<<<1, 128>>>(bsum);                                        // #5
    csr_scan3<<<NSCAN, SCAN_BLK>>>(rowptr, bsum);                       // #6
    csr_fill<<<(ETOT + 255) / 256, 256>>>(ei, rowptr, fill, csr_src, epos); // #7

    // ---- layer 0 rest (gather applies bias B[0] + relu -> buf0) ----
    run_layer_rest<10, 24>(AS[0], AD[0], B[0], ei, epos, h, h2, as, ad, ebuf, smaxu, rowptr, csr_src, buf0);

    // ---- layers 1-4 ----
    launch_gemm<240, 120>(buf0, W[1], h, h2);
    run_layer_rest< 5, 24>(AS[1], AD[1], B[1], ei, epos, h, h2, as, ad, ebuf, smaxu, rowptr, csr_src, buf1);

    launch_gemm<120,  48>(buf1, W[2], h, h2);
    run_layer_rest< 2, 24>(AS[2], AD[2], B[2], ei, epos, h, h2, as, ad, ebuf, smaxu, rowptr, csr_src, buf0);

    launch_gemm< 48,  24>(buf0, W[3], h, h2);
    run_layer_rest< 1, 24>(AS[3], AD[3], B[3], ei, epos, h, h2, as, ad, ebuf, smaxu, rowptr, csr_src, buf1);

    launch_gemm< 24,  12>(buf1, W[4], h, h2);
    run_layer_rest< 1, 12>(AS[4], AD[4], B[4], ei, epos, h, h2, as, ad, ebuf, smaxu, rowptr, csr_src, (float*)d_out);
}

// round 14
// speedup vs baseline: 1.1526x; 1.0774x over previous
#include <cuda_runtime.h>
#include <cuda_bf16.h>
#include <cuda_fp16.h>

#define NNODES 100000
#define NEDGES 800000
#define ETOT   900000
#define MAXHC  240
#define MAXH   10
#define NEG_SLOPE 0.2f
#define SCAN_BLK 1024
#define NSCAN ((NNODES + SCAN_BLK - 1) / SCAN_BLK)   // 98

// ---------------- scratch (device globals; no allocation allowed) ----------------
__device__ __half   g_h2  [NNODES * MAXHC];     // fp16 h (alpha + gather)
__device__ float    g_buf0[NNODES * MAXHC];
__device__ float    g_buf1[NNODES * MAXHC];
__device__ float    g_as  [NNODES * MAXH];
__device__ float    g_ad  [NNODES * MAXH];
__device__ float    g_e   [ETOT   * MAXH];      // per-edge exp values (CSR order)
__device__ unsigned g_smaxu[MAXH];              // per-head global max (encoded)
// CSR (built once per launch)
__device__ int g_rowptr [NNODES + 1];
__device__ int g_cnt    [NNODES];
__device__ int g_fill   [NNODES];
__device__ int g_csr_src[ETOT];
__device__ int g_epos   [ETOT];                 // edge id -> csr position
__device__ int g_bsum   [NSCAN];

// ---------------- helpers ----------------
__device__ __forceinline__ unsigned enc_f(float v) {
    unsigned u = __float_as_uint(v);
    return (u & 0x80000000u) ? ~u : (u | 0x80000000u);
}
__device__ __forceinline__ float dec_f(unsigned u) {
    return __uint_as_float((u & 0x80000000u) ? (u ^ 0x80000000u) : ~u);
}

// split fp32 into two tf32 values (3xTF32 trick); x - hi is exact in fp32.
__device__ __forceinline__ void split_tf32(float x, unsigned& hi, unsigned& lo) {
    asm("cvt.rna.tf32.f32 %0, %1;" : "=r"(hi) : "f"(x));
    float r = x - __uint_as_float(hi);
    asm("cvt.rna.tf32.f32 %0, %1;" : "=r"(lo) : "f"(r));
}

__device__ __forceinline__ void mma_tf32(float* d, const unsigned* a, const unsigned* b) {
    asm volatile("mma.sync.aligned.m16n8k8.row.col.f32.tf32.tf32.f32 "
        "{%0,%1,%2,%3}, {%4,%5,%6,%7}, {%8,%9}, {%0,%1,%2,%3};"
        : "+f"(d[0]), "+f"(d[1]), "+f"(d[2]), "+f"(d[3])
        : "r"(a[0]), "r"(a[1]), "r"(a[2]), "r"(a[3]), "r"(b[0]), "r"(b[1]));
}

#define CP_ASYNC16(dst, src, sz) \
    asm volatile("cp.async.ca.shared.global [%0], [%1], 16, %2;" \
                 :: "r"(dst), "l"(src), "r"(sz) : "memory")
#define CP_COMMIT()  asm volatile("cp.async.commit_group;" ::: "memory")
#define CP_WAIT0()   asm volatile("cp.async.wait_group 0;" ::: "memory")

// ================= CSR build (once per launch) =================
__global__ __launch_bounds__(256) void csr_zero(int* cnt, int* fill, unsigned* smaxu) {
    int i = blockIdx.x * blockDim.x + threadIdx.x;
    if (i < NNODES) { cnt[i] = 0; fill[i] = 0; }
    if (i < MAXH) smaxu[i] = 0u;
}

__global__ __launch_bounds__(256) void csr_hist(const int* __restrict__ ei, int* cnt) {
    int e = blockIdx.x * blockDim.x + threadIdx.x;
    if (e >= ETOT) return;
    int d = (e < NEDGES) ? __ldg(ei + NEDGES + e) : (e - NEDGES);
    atomicAdd(&cnt[d], 1);
}

__global__ __launch_bounds__(SCAN_BLK) void csr_scan1(const int* __restrict__ cnt,
                                                      int* rowptr, int* bsum) {
    __shared__ int sh[SCAN_BLK];
    int gi = blockIdx.x * SCAN_BLK + threadIdx.x;
    int v = (gi < NNODES) ? cnt[gi] : 0;
    sh[threadIdx.x] = v;
    __syncthreads();
    for (int off = 1; off < SCAN_BLK; off <<= 1) {
        int t = (threadIdx.x >= off) ? sh[threadIdx.x - off] : 0;
        __syncthreads();
        sh[threadIdx.x] += t;
        __syncthreads();
    }
    if (gi < NNODES) rowptr[gi] = sh[threadIdx.x] - v;
    if (threadIdx.x == SCAN_BLK - 1) bsum[blockIdx.x] = sh[threadIdx.x];
}

__global__ __launch_bounds__(128) void csr_scan2(int* bsum) {
    __shared__ int sh[128];
    int v = (threadIdx.x < NSCAN) ? bsum[threadIdx.x] : 0;
    sh[threadIdx.x] = v;
    __syncthreads();
    for (int off = 1; off < 128; off <<= 1) {
        int t = (threadIdx.x >= off) ? sh[threadIdx.x - off] : 0;
        __syncthreads();
        sh[threadIdx.x] += t;
        __syncthreads();
    }
    if (threadIdx.x < NSCAN) bsum[threadIdx.x] = sh[threadIdx.x] - v;
}

__global__ __launch_bounds__(SCAN_BLK) void csr_scan3(int* rowptr, const int* __restrict__ bsum) {
    int gi = blockIdx.x * SCAN_BLK + threadIdx.x;
    if (gi < NNODES) rowptr[gi] += bsum[blockIdx.x];
    if (gi == 0) rowptr[NNODES] = ETOT;
}

__global__ __launch_bounds__(256) void csr_fill(const int* __restrict__ ei,
                                                const int* __restrict__ rowptr,
                                                int* fill, int* csr_src, int* epos) {
    int e = blockIdx.x * blockDim.x + threadIdx.x;
    if (e >= ETOT) return;
    int s, d;
    if (e < NEDGES) { s = __ldg(ei + e); d = __ldg(ei + NEDGES + e); }
    else            { s = e - NEDGES; d = s; }
    int pos = rowptr[d] + atomicAdd(&fill[d], 1);
    csr_src[pos] = s;
    epos[e] = pos;
}

// ================= tf32 tensor-core GEMM (round-11 layout), fp16 output =================
template<int K, int N>
__global__ __launch_bounds__(256, 3) void gemm_tf32_kernel(
    const float* __restrict__ A, const float* __restrict__ W,
    __half* __restrict__ out2, int M)
{
    __shared__ float    As[2][128][12];
    __shared__ unsigned Bh[2][8][72];
    __shared__ unsigned Bl[2][8][72];

    const int tid  = threadIdx.x;
    const int lane = tid & 31;
    const int warp = tid >> 5;
    const int wm   = warp & 3;
    const int wn   = warp >> 2;
    const int row0 = blockIdx.y * 128;
    const int col0 = blockIdx.x * 64;

    float acc[2][4][4];
#pragma unroll
    for (int mt = 0; mt < 2; mt++)
#pragma unroll
        for (int nt = 0; nt < 4; nt++)
#pragma unroll
            for (int i = 0; i < 4; i++) acc[mt][nt][i] = 0.f;

    const int arow = tid >> 1;
    const int ah4  = (tid & 1) * 4;
    const int gr   = row0 + arow;
    const unsigned a_sz = (gr < M) ? 16u : 0u;
    const float* a_src = A + (long)(gr < M ? gr : 0) * K + ah4;
    unsigned a_dst[2];
    a_dst[0] = (unsigned)__cvta_generic_to_shared(&As[0][arow][ah4]);
    a_dst[1] = (unsigned)__cvta_generic_to_shared(&As[1][arow][ah4]);

    const int bk   = (tid & 127) >> 4;
    const int bnc  = tid & 15;
    const int gcol = col0 + bnc * 4;
    const int rem  = N - gcol;

    auto ldg_b = [&](int k0) -> float4 {
        float4 v = make_float4(0.f, 0.f, 0.f, 0.f);
        if (tid < 128 && rem > 0) {
            const float* p = W + (long)(k0 + bk) * N + gcol;
            if (rem >= 4) v = *(const float4*)p;
            else { v.x = p[0]; if (rem > 1) v.y = p[1]; if (rem > 2) v.z = p[2]; }
        }
        return v;
    };
    auto store_b = [&](int buf, float4 v) {
        if (tid < 128) {
            unsigned h0, l0, h1, l1, h2, l2, h3, l3;
            split_tf32(v.x, h0, l0); split_tf32(v.y, h1, l1);
            split_tf32(v.z, h2, l2); split_tf32(v.w, h3, l3);
            unsigned* ph = &Bh[buf][bk][bnc * 4];
            unsigned* pl = &Bl[buf][bk][bnc * 4];
            ph[0] = h0; ph[1] = h1; ph[2] = h2; ph[3] = h3;
            pl[0] = l0; pl[1] = l1; pl[2] = l2; pl[3] = l3;
        }
    };

    constexpr int NK = K / 8;

    CP_ASYNC16(a_dst[0], a_src, a_sz);
    CP_COMMIT();
    store_b(0, ldg_b(0));
    CP_WAIT0();
    __syncthreads();

#pragma unroll 1
    for (int s = 0; s < NK; s++) {
        const bool more = (s + 1 < NK);
        float4 bn;
        if (more) {
            const int k0n = (s + 1) * 8;
            CP_ASYNC16(a_dst[(s + 1) & 1], a_src + k0n, a_sz);
            CP_COMMIT();
            bn = ldg_b(k0n);
        }

        const int buf = s & 1;
        unsigned ahf[2][4], alf[2][4];
#pragma unroll
        for (int mt = 0; mt < 2; mt++) {
            const float* ap = &As[buf][wm * 32 + mt * 16 + (lane >> 2)][lane & 3];
            split_tf32(ap[0],   ahf[mt][0], alf[mt][0]);
            split_tf32(ap[96],  ahf[mt][1], alf[mt][1]);
            split_tf32(ap[4],   ahf[mt][2], alf[mt][2]);
            split_tf32(ap[100], ahf[mt][3], alf[mt][3]);
        }
#pragma unroll
        for (int nt = 0; nt < 4; nt++) {
            const int ci = wn * 32 + nt * 8 + (lane >> 2);
            const int ki = lane & 3;
            unsigned bh[2], bl[2];
            bh[0] = Bh[buf][ki][ci];     bh[1] = Bh[buf][ki + 4][ci];
            bl[0] = Bl[buf][ki][ci];     bl[1] = Bl[buf][ki + 4][ci];
#pragma unroll
            for (int mt = 0; mt < 2; mt++) {
                mma_tf32(acc[mt][nt], ahf[mt], bh);
                mma_tf32(acc[mt][nt], ahf[mt], bl);
                mma_tf32(acc[mt][nt], alf[mt], bh);
            }
        }

        if (more) {
            store_b((s + 1) & 1, bn);
            CP_WAIT0();
            __syncthreads();
        }
    }

    // ---- epilogue: fp16-only guarded stores ----
#pragma unroll
    for (int mt = 0; mt < 2; mt++) {
#pragma unroll
        for (int nt = 0; nt < 4; nt++) {
            int r = row0 + wm * 32 + mt * 16 + (lane >> 2);
            int c = col0 + wn * 32 + nt * 8 + (lane & 3) * 2;
            if (c + 1 < N) {
                if (r < M)
                    *(__half2*)(out2 + (long)r * N + c) =
                        __floats2half2_rn(acc[mt][nt][0], acc[mt][nt][1]);
                if (r + 8 < M)
                    *(__half2*)(out2 + (long)(r + 8) * N + c) =
                        __floats2half2_rn(acc[mt][nt][2], acc[mt][nt][3]);
            }
        }
    }
}

// ================= alpha (fp16 h) + per-head global max =================
template<int H, int C>
__global__ __launch_bounds__(256) void alpha_kernel(
    const __half* __restrict__ h2, const float* __restrict__ a_s,
    const float* __restrict__ a_d, float* __restrict__ alpha_s,
    float* __restrict__ alpha_d, unsigned* __restrict__ smaxu)
{
    __shared__ unsigned s_max[H];
    if (threadIdx.x < H) s_max[threadIdx.x] = 0u;
    __syncthreads();

    int idx = blockIdx.x * blockDim.x + threadIdx.x;
    if (idx < NNODES * H) {
        int node = idx / H;
        int hh = idx - node * H;
        const uint2* hp   = (const uint2*)(h2 + (long)node * H * C + hh * C);  // 4 halves
        const float4* asp = (const float4*)(a_s + hh * C);
        const float4* adp = (const float4*)(a_d + hh * C);
        float ss = 0.f, sd = 0.f;
#pragma unroll
        for (int c = 0; c < C / 4; c++) {
            uint2 raw = __ldg(hp + c);
            float2 f0 = __half22float2(*reinterpret_cast<__half2*>(&raw.x));
            float2 f1 = __half22float2(*reinterpret_cast<__half2*>(&raw.y));
            float4 s4 = __ldg(asp + c);
            float4 d4 = __ldg(adp + c);
            ss += f0.x * s4.x + f0.y * s4.y + f1.x * s4.z + f1.y * s4.w;
            sd += f0.x * d4.x + f0.y * d4.y + f1.x * d4.z + f1.y * d4.w;
        }
        alpha_s[idx] = ss;
        alpha_d[idx] = sd;
        atomicMax(&s_max[hh], enc_f(ss));
    }
    __syncthreads();
    if (threadIdx.x < H)
        atomicMax(&smaxu[threadIdx.x], s_max[threadIdx.x]);
}

// ================= fused edge pass: exp(e - m_ub), CSR-ordered store =================
template<int H>
__global__ __launch_bounds__(256) void edge_fused(
    const int* __restrict__ ei, const int* __restrict__ epos,
    const float* __restrict__ as, const float* __restrict__ ad,
    const unsigned* __restrict__ smaxu, float* __restrict__ ebuf)
{
    int idx = blockIdx.x * blockDim.x + threadIdx.x;
    if (idx >= ETOT * H) return;
    int e  = idx / H;
    int hh = idx - e * H;
    int s, d;
    if (e < NEDGES) { s = __ldg(ei + e); d = __ldg(ei + NEDGES + e); }
    else            { s = e - NEDGES; d = s; }
    float asv = __ldg(as + s * H + hh);
    float adv = __ldg(ad + d * H + hh);
    float ev = asv + adv;
    ev = (ev > 0.f) ? ev : NEG_SLOPE * ev;
    float mb = dec_f(__ldg(smaxu + hh)) + adv;
    mb = (mb > 0.f) ? mb : NEG_SLOPE * mb;
    float ex = __expf(ev - mb);
    int pos = __ldg(epos + e);
    ebuf[(long)pos * H + hh] = ex;      // scattered write (fire-and-forget)
}

// ================= CSR gather (fp16 h) + bias + ReLU epilogue =================
template<int H, int C>
__global__ __launch_bounds__(256) void node_gather(
    const int* __restrict__ rowptr, const int* __restrict__ csr_src,
    const float* __restrict__ ex, const __half* __restrict__ h2,
    const float* __restrict__ bias, float* __restrict__ out,
    unsigned* __restrict__ smaxu)
{
    constexpr int NCH = H * C / 4;
    constexpr int HC  = H * C;
    long idx = (long)blockIdx.x * blockDim.x + threadIdx.x;
    if (idx < MAXH) smaxu[idx] = 0u;
    if (idx >= (long)NNODES * NCH) return;
    int n = (int)(idx / NCH);
    int q = (int)(idx - (long)n * NCH);
    int head = q / (C / 4);

    int beg = __ldg(rowptr + n);
    int end = __ldg(rowptr + n + 1);
    float4 acc = make_float4(0.f, 0.f, 0.f, 0.f);
    float zs = 0.f;

    auto accum = [&](int j) {
        int s0 = __ldg(csr_src + j);
        float a0 = __ldg(ex + (long)j * H + head);
        uint2 raw = *(const uint2*)(h2 + (long)s0 * HC + q * 4);
        float2 f0 = __half22float2(*reinterpret_cast<__half2*>(&raw.x));
        float2 f1 = __half22float2(*reinterpret_cast<__half2*>(&raw.y));
        acc.x += f0.x * a0; acc.y += f0.y * a0;
        acc.z += f1.x * a0; acc.w += f1.y * a0;
        zs += a0;
    };

    int j = beg;
    for (; j + 1 < end; j += 2) { accum(j); accum(j + 1); }
    if (j < end) accum(j);

    float rzv = __frcp_rn(zs);
    const float4 bv = __ldg((const float4*)(bias + q * 4));
    *(float4*)(out + (long)n * HC + q * 4) =
        make_float4(fmaxf(acc.x * rzv + bv.x, 0.f),
                    fmaxf(acc.y * rzv + bv.y, 0.f),
                    fmaxf(acc.z * rzv + bv.z, 0.f),
                    fmaxf(acc.w * rzv + bv.w, 0.f));
}

// ================= per-layer templated driver (minus GEMM) =================
template<int H, int C>
static void run_layer_rest(const float* a_s, const float* a_d, const float* bias,
                           const int* ei, const int* epos,
                           const __half* h2, float* as, float* ad,
                           float* ebuf, unsigned* smaxu,
                           const int* rowptr, const int* csr_src,
                           float* outb)
{
    constexpr int HC = H * C;
    {
        int n = NNODES * H;
        alpha_kernel<H, C><<<(n + 255) / 256, 256>>>(h2, a_s, a_d, as, ad, smaxu);
    }
    {
        int n = ETOT * H;
        edge_fused<H><<<(n + 255) / 256, 256>>>(ei, epos, as, ad, smaxu, ebuf);
    }
    {
        long total = (long)NNODES * (HC / 4);
        int blocks = (int)((total + 255) / 256);
        node_gather<H, C><<<blocks, 256>>>(rowptr, csr_src, ebuf, h2, bias, outb, smaxu);
    }
}

template<int K, int N>
static void launch_gemm(const float* A, const float* W, __half* out2) {
    dim3 grid((N + 63) / 64, (NNODES + 127) / 128);
    gemm_tf32_kernel<K, N><<<grid, 256>>>(A, W, out2, NNODES);
}

// ================= host orchestration =================
extern "C" void kernel_launch(void* const* d_in, const int* in_sizes, int n_in,
                              void* d_out, int out_size)
{
    const float* x  = (const float*)d_in[0];
    const int*   ei = (const int*)d_in[1];

    float *buf0, *buf1, *as, *ad, *ebuf;
    __half* h2;
    unsigned* smaxu;
    int *rowptr, *cnt, *fill, *csr_src, *epos, *bsum;
    {
        void* p;
        cudaGetSymbolAddress(&p, g_h2);      h2      = (__half*)p;
        cudaGetSymbolAddress(&p, g_buf0);    buf0    = (float*)p;
        cudaGetSymbolAddress(&p, g_buf1);    buf1    = (float*)p;
        cudaGetSymbolAddress(&p, g_as);      as      = (float*)p;
        cudaGetSymbolAddress(&p, g_ad);      ad      = (float*)p;
        cudaGetSymbolAddress(&p, g_e);       ebuf    = (float*)p;
        cudaGetSymbolAddress(&p, g_smaxu);   smaxu   = (unsigned*)p;
        cudaGetSymbolAddress(&p, g_rowptr);  rowptr  = (int*)p;
        cudaGetSymbolAddress(&p, g_cnt);     cnt     = (int*)p;
        cudaGetSymbolAddress(&p, g_fill);    fill    = (int*)p;
        cudaGetSymbolAddress(&p, g_csr_src); csr_src = (int*)p;
        cudaGetSymbolAddress(&p, g_epos);    epos    = (int*)p;
        cudaGetSymbolAddress(&p, g_bsum);    bsum    = (int*)p;
    }

    const float* W[5]; const float* B[5]; const float* AS[5]; const float* AD[5];
    for (int i = 0; i < 5; i++) {
        W[i]  = (const float*)d_in[3 + 4 * i];
        B[i]  = (const float*)d_in[4 + 4 * i];
        AS[i] = (const float*)d_in[5 + 4 * i];
        AD[i] = (const float*)d_in[6 + 4 * i];
    }

    // ---- CSR build interleaved with layer-0 GEMM (independent) ----
    csr_zero<<<(NNODES + 255) / 256, 256>>>(cnt, fill, smaxu);          // #1
    csr_hist<<<(ETOT + 255) / 256, 256>>>(ei, cnt);                     // #2
    csr_scan1<<<NSCAN, SCAN_BLK>>>(cnt, rowptr, bsum);                  // #3
    launch_gemm< 32, 240>(x, W[0], h2);                                 // #4 (profiled)
    csr_scan2<<<1, 128>>>(bsum);                                        // #5
    csr_scan3<<<NSCAN, SCAN_BLK>>>(rowptr, bsum);                       // #6
    csr_fill<<<(ETOT + 255) / 256, 256>>>(ei, rowptr, fill, csr_src, epos); // #7

    // ---- layer 0 rest (gather applies bias B[0] + relu -> buf0) ----
    run_layer_rest<10, 24>(AS[0], AD[0], B[0], ei, epos, h2, as, ad, ebuf, smaxu, rowptr, csr_src, buf0);

    // ---- layers 1-4 ----
    launch_gemm<240, 120>(buf0, W[1], h2);
    run_layer_rest< 5, 24>(AS[1], AD[1], B[1], ei, epos, h2, as, ad, ebuf, smaxu, rowptr, csr_src, buf1);

    launch_gemm<120,  48>(buf1, W[2], h2);
    run_layer_rest< 2, 24>(AS[2], AD[2], B[2], ei, epos, h2, as, ad, ebuf, smaxu, rowptr, csr_src, buf0);

    launch_gemm< 48,  24>(buf0, W[3], h2);
    run_layer_rest< 1, 24>(AS[3], AD[3], B[3], ei, epos, h2, as, ad, ebuf, smaxu, rowptr, csr_src, buf1);

    launch_gemm< 24,  12>(buf1, W[4], h2);
    run_layer_rest< 1, 12>(AS[4], AD[4], B[4], ei, epos, h2, as, ad, ebuf, smaxu, rowptr, csr_src, (float*)d_out);
}

// round 15
// speedup vs baseline: 1.5178x; 1.3168x over previous
#include <cuda_runtime.h>
#include <cuda_bf16.h>
#include <cuda_fp16.h>

#define NNODES 100000
#define NEDGES 800000
#define ETOT   900000
#define MAXHC  240
#define MAXH   10
#define NEG_SLOPE 0.2f
#define SCAN_BLK 1024
#define NSCAN ((NNODES + SCAN_BLK - 1) / SCAN_BLK)   // 98

// W sizes (transposed fp16): Wt[n*K + k]
#define WT_S0 (32*240)
#define WT_S1 (240*120)
#define WT_S2 (120*48)
#define WT_S3 (48*24)
#define WT_S4 (24*12)
#define WT_O0 0
#define WT_O1 (WT_O0 + WT_S0)
#define WT_O2 (WT_O1 + WT_S1)
#define WT_O3 (WT_O2 + WT_S2)
#define WT_O4 (WT_O3 + WT_S3)
#define WT_TOT (WT_O4 + WT_S4)

// ---------------- scratch (device globals; no allocation allowed) ----------------
__device__ __half   g_h2   [NNODES * MAXHC];    // fp16 h (alpha + gather)
__device__ __half   g_xh   [NNODES * 32];       // fp16 copy of input x
__device__ __half   g_bufh0[NNODES * MAXHC];    // fp16 layer outputs (ping)
__device__ __half   g_bufh1[NNODES * MAXHC];    // fp16 layer outputs (pong)
__device__ __half   g_wt   [WT_TOT];            // fp16 transposed weights
__device__ float    g_as   [NNODES * MAXH];
__device__ float    g_ad   [NNODES * MAXH];
__device__ float    g_e    [ETOT   * MAXH];     // per-edge exp values (CSR order)
__device__ unsigned g_smaxu[MAXH];              // per-head global max (encoded)
// CSR (built once per launch)
__device__ int g_rowptr [NNODES + 1];
__device__ int g_cnt    [NNODES];
__device__ int g_fill   [NNODES];
__device__ int g_csr_src[ETOT];
__device__ int g_epos   [ETOT];                 // edge id -> csr position
__device__ int g_bsum   [NSCAN];

// ---------------- helpers ----------------
__device__ __forceinline__ unsigned enc_f(float v) {
    unsigned u = __float_as_uint(v);
    return (u & 0x80000000u) ? ~u : (u | 0x80000000u);
}
__device__ __forceinline__ float dec_f(unsigned u) {
    return __uint_as_float((u & 0x80000000u) ? (u ^ 0x80000000u) : ~u);
}

__device__ __forceinline__ void mma_f16(float* d, const unsigned* a, const unsigned* b) {
    asm volatile("mma.sync.aligned.m16n8k16.row.col.f32.f16.f16.f32 "
        "{%0,%1,%2,%3}, {%4,%5,%6,%7}, {%8,%9}, {%0,%1,%2,%3};"
        : "+f"(d[0]), "+f"(d[1]), "+f"(d[2]), "+f"(d[3])
        : "r"(a[0]), "r"(a[1]), "r"(a[2]), "r"(a[3]), "r"(b[0]), "r"(b[1]));
}

// ================= input conversions (once per launch) =================
__global__ __launch_bounds__(256) void cvt_x_kernel(const float* __restrict__ x,
                                                    __half* __restrict__ xh) {
    int i = blockIdx.x * blockDim.x + threadIdx.x;
    if (i < NNODES * 32) xh[i] = __float2half(x[i]);
}

// Wt[n*K + k] = (half) W[k*N + n], for all 5 layers in one launch.
__global__ __launch_bounds__(256) void wt_convert_kernel(
    const float* __restrict__ W0, const float* __restrict__ W1,
    const float* __restrict__ W2, const float* __restrict__ W3,
    const float* __restrict__ W4, __half* __restrict__ wt)
{
    int i = blockIdx.x * blockDim.x + threadIdx.x;
    if (i >= WT_TOT) return;
    const float* W; int K, N, off;
    if      (i < WT_O1) { W = W0; K = 32;  N = 240; off = WT_O0; }
    else if (i < WT_O2) { W = W1; K = 240; N = 120; off = WT_O1; }
    else if (i < WT_O3) { W = W2; K = 120; N = 48;  off = WT_O2; }
    else if (i < WT_O4) { W = W3; K = 48;  N = 24;  off = WT_O3; }
    else                { W = W4; K = 24;  N = 12;  off = WT_O4; }
    int li = i - off;
    int n = li / K, k = li - n * K;
    wt[i] = __float2half(W[k * N + n]);
}

// ================= CSR build (once per launch) =================
__global__ __launch_bounds__(256) void csr_zero(int* cnt, int* fill, unsigned* smaxu) {
    int i = blockIdx.x * blockDim.x + threadIdx.x;
    if (i < NNODES) { cnt[i] = 0; fill[i] = 0; }
    if (i < MAXH) smaxu[i] = 0u;
}

__global__ __launch_bounds__(256) void csr_hist(const int* __restrict__ ei, int* cnt) {
    int e = blockIdx.x * blockDim.x + threadIdx.x;
    if (e >= ETOT) return;
    int d = (e < NEDGES) ? __ldg(ei + NEDGES + e) : (e - NEDGES);
    atomicAdd(&cnt[d], 1);
}

__global__ __launch_bounds__(SCAN_BLK) void csr_scan1(const int* __restrict__ cnt,
                                                      int* rowptr, int* bsum) {
    __shared__ int sh[SCAN_BLK];
    int gi = blockIdx.x * SCAN_BLK + threadIdx.x;
    int v = (gi < NNODES) ? cnt[gi] : 0;
    sh[threadIdx.x] = v;
    __syncthreads();
    for (int off = 1; off < SCAN_BLK; off <<= 1) {
        int t = (threadIdx.x >= off) ? sh[threadIdx.x - off] : 0;
        __syncthreads();
        sh[threadIdx.x] += t;
        __syncthreads();
    }
    if (gi < NNODES) rowptr[gi] = sh[threadIdx.x] - v;
    if (threadIdx.x == SCAN_BLK - 1) bsum[blockIdx.x] = sh[threadIdx.x];
}

__global__ __launch_bounds__(128) void csr_scan2(int* bsum) {
    __shared__ int sh[128];
    int v = (threadIdx.x < NSCAN) ? bsum[threadIdx.x] : 0;
    sh[threadIdx.x] = v;
    __syncthreads();
    for (int off = 1; off < 128; off <<= 1) {
        int t = (threadIdx.x >= off) ? sh[threadIdx.x - off] : 0;
        __syncthreads();
        sh[threadIdx.x] += t;
        __syncthreads();
    }
    if (threadIdx.x < NSCAN) bsum[threadIdx.x] = sh[threadIdx.x] - v;
}

__global__ __launch_bounds__(SCAN_BLK) void csr_scan3(int* rowptr, const int* __restrict__ bsum) {
    int gi = blockIdx.x * SCAN_BLK + threadIdx.x;
    if (gi < NNODES) rowptr[gi] += bsum[blockIdx.x];
    if (gi == 0) rowptr[NNODES] = ETOT;
}

__global__ __launch_bounds__(256) void csr_fill(const int* __restrict__ ei,
                                                const int* __restrict__ rowptr,
                                                int* fill, int* csr_src, int* epos) {
    int e = blockIdx.x * blockDim.x + threadIdx.x;
    if (e >= ETOT) return;
    int s, d;
    if (e < NEDGES) { s = __ldg(ei + e); d = __ldg(ei + NEDGES + e); }
    else            { s = e - NEDGES; d = s; }
    int pos = rowptr[d] + atomicAdd(&fill[d], 1);
    csr_src[pos] = s;
    epos[e] = pos;
}

// ================= fp16 tensor-core GEMM: out[M,N] = A[M,K] @ Wt[N,K]^T =================
// Block 128x64, 8 warps (4m x 2n), warp tile 32x32 (2x4 m16n8k16 frags).
// A fp16 [M][K] row-major, Wt fp16 [N][K] (k-contiguous). Double-buffered,
// register-prefetched. Pad-24 smem rows: conflict-free frags + 16B-aligned stores.
template<int K, int N>
__global__ __launch_bounds__(256, 4) void gemm_fp16_kernel(
    const __half* __restrict__ A, const __half* __restrict__ Wt,
    __half* __restrict__ out2, int M)
{
    __shared__ __half As[2][128][24];
    __shared__ __half Bs[2][64][24];

    const int tid  = threadIdx.x;
    const int lane = tid & 31;
    const int warp = tid >> 5;
    const int wm   = warp & 3;
    const int wn   = warp >> 2;
    const int row0 = blockIdx.y * 128;
    const int col0 = blockIdx.x * 64;

    float acc[2][4][4];
#pragma unroll
    for (int mt = 0; mt < 2; mt++)
#pragma unroll
        for (int nt = 0; nt < 4; nt++)
#pragma unroll
            for (int i = 0; i < 4; i++) acc[mt][nt][i] = 0.f;

    // ---- A loader: row = tid>>1, 8 halves at (tid&1)*8 ----
    const int arow = tid >> 1;
    const int ako  = (tid & 1) * 8;
    const int gr   = row0 + arow;
    const bool a_ok = (gr < M);
    const __half* a_src = A + (long)(a_ok ? gr : 0) * K + ako;

    // ---- B loader (tid<128): n = tid>>1, 8 halves at (tid&1)*8 ----
    const int bn  = tid >> 1;            // valid 0..63 for tid<128
    const int bko = (tid & 1) * 8;
    const int gn  = col0 + bn;
    const bool b_ok = (tid < 128) && (gn < N);
    const __half* b_src = Wt + (long)(b_ok ? gn : 0) * K + bko;

    auto ldg_a = [&](int k0) -> uint4 {
        if (a_ok && k0 + ako < K) return *(const uint4*)(a_src + k0);
        return make_uint4(0u, 0u, 0u, 0u);
    };
    auto ldg_b = [&](int k0) -> uint4 {
        if (b_ok && k0 + bko < K) return *(const uint4*)(b_src + k0);
        return make_uint4(0u, 0u, 0u, 0u);
    };
    auto store_a = [&](int buf, uint4 v) {
        *(uint4*)&As[buf][arow][ako] = v;            // 16B-aligned (48B row stride)
    };
    auto store_b = [&](int buf, uint4 v) {
        if (tid < 128) *(uint4*)&Bs[buf][bn][bko] = v;
    };

    constexpr int NK = (K + 15) / 16;

    store_a(0, ldg_a(0));
    store_b(0, ldg_b(0));
    __syncthreads();

#pragma unroll 1
    for (int s = 0; s < NK; s++) {
        const bool more = (s + 1 < NK);
        uint4 an, bnx;
        if (more) {
            const int k0n = (s + 1) * 16;
            an  = ldg_a(k0n);
            bnx = ldg_b(k0n);
        }

        const int buf = s & 1;
        const int kq = (lane & 3) * 2;
        // A fragments (2 m-tiles x 4 regs)
        unsigned af[2][4];
#pragma unroll
        for (int mt = 0; mt < 2; mt++) {
            const int r = wm * 32 + mt * 16 + (lane >> 2);
            af[mt][0] = *(const unsigned*)&As[buf][r][kq];
            af[mt][1] = *(const unsigned*)&As[buf][r + 8][kq];
            af[mt][2] = *(const unsigned*)&As[buf][r][kq + 8];
            af[mt][3] = *(const unsigned*)&As[buf][r + 8][kq + 8];
        }
        // B fragments + mma
#pragma unroll
        for (int nt = 0; nt < 4; nt++) {
            const int ci = wn * 32 + nt * 8 + (lane >> 2);
            unsigned bf[2];
            bf[0] = *(const unsigned*)&Bs[buf][ci][kq];
            bf[1] = *(const unsigned*)&Bs[buf][ci][kq + 8];
#pragma unroll
            for (int mt = 0; mt < 2; mt++)
                mma_f16(acc[mt][nt], af[mt], bf);
        }

        if (more) {
            store_a((s + 1) & 1, an);
            store_b((s + 1) & 1, bnx);
            __syncthreads();
        }
    }

    // ---- epilogue: fp16 guarded stores ----
#pragma unroll
    for (int mt = 0; mt < 2; mt++) {
#pragma unroll
        for (int nt = 0; nt < 4; nt++) {
            int r = row0 + wm * 32 + mt * 16 + (lane >> 2);
            int c = col0 + wn * 32 + nt * 8 + (lane & 3) * 2;
            if (c + 1 < N) {
                if (r < M)
                    *(__half2*)(out2 + (long)r * N + c) =
                        __floats2half2_rn(acc[mt][nt][0], acc[mt][nt][1]);
                if (r + 8 < M)
                    *(__half2*)(out2 + (long)(r + 8) * N + c) =
                        __floats2half2_rn(acc[mt][nt][2], acc[mt][nt][3]);
            }
        }
    }
}

// ================= alpha (fp16 h) + per-head global max =================
template<int H, int C>
__global__ __launch_bounds__(256) void alpha_kernel(
    const __half* __restrict__ h2, const float* __restrict__ a_s,
    const float* __restrict__ a_d, float* __restrict__ alpha_s,
    float* __restrict__ alpha_d, unsigned* __restrict__ smaxu)
{
    __shared__ unsigned s_max[H];
    if (threadIdx.x < H) s_max[threadIdx.x] = 0u;
    __syncthreads();

    int idx = blockIdx.x * blockDim.x + threadIdx.x;
    if (idx < NNODES * H) {
        int node = idx / H;
        int hh = idx - node * H;
        const uint2* hp   = (const uint2*)(h2 + (long)node * H * C + hh * C);
        const float4* asp = (const float4*)(a_s + hh * C);
        const float4* adp = (const float4*)(a_d + hh * C);
        float ss = 0.f, sd = 0.f;
#pragma unroll
        for (int c = 0; c < C / 4; c++) {
            uint2 raw = __ldg(hp + c);
            float2 f0 = __half22float2(*reinterpret_cast<__half2*>(&raw.x));
            float2 f1 = __half22float2(*reinterpret_cast<__half2*>(&raw.y));
            float4 s4 = __ldg(asp + c);
            float4 d4 = __ldg(adp + c);
            ss += f0.x * s4.x + f0.y * s4.y + f1.x * s4.z + f1.y * s4.w;
            sd += f0.x * d4.x + f0.y * d4.y + f1.x * d4.z + f1.y * d4.w;
        }
        alpha_s[idx] = ss;
        alpha_d[idx] = sd;
        atomicMax(&s_max[hh], enc_f(ss));
    }
    __syncthreads();
    if (threadIdx.x < H)
        atomicMax(&smaxu[threadIdx.x], s_max[threadIdx.x]);
}

// ================= fused edge pass: exp(e - m_ub), CSR-ordered store =================
template<int H>
__global__ __launch_bounds__(256) void edge_fused(
    const int* __restrict__ ei, const int* __restrict__ epos,
    const float* __restrict__ as, const float* __restrict__ ad,
    const unsigned* __restrict__ smaxu, float* __restrict__ ebuf)
{
    int idx = blockIdx.x * blockDim.x + threadIdx.x;
    if (idx >= ETOT * H) return;
    int e  = idx / H;
    int hh = idx - e * H;
    int s, d;
    if (e < NEDGES) { s = __ldg(ei + e); d = __ldg(ei + NEDGES + e); }
    else            { s = e - NEDGES; d = s; }
    float asv = __ldg(as + s * H + hh);
    float adv = __ldg(ad + d * H + hh);
    float ev = asv + adv;
    ev = (ev > 0.f) ? ev : NEG_SLOPE * ev;
    float mb = dec_f(__ldg(smaxu + hh)) + adv;
    mb = (mb > 0.f) ? mb : NEG_SLOPE * mb;
    float ex = __expf(ev - mb);
    int pos = __ldg(epos + e);
    ebuf[(long)pos * H + hh] = ex;      // scattered write (fire-and-forget)
}

// ================= CSR gather (fp16 h) + bias + ReLU; fp16 or fp32 output =================
template<int H, int C, bool HALF_OUT>
__global__ __launch_bounds__(256) void node_gather(
    const int* __restrict__ rowptr, const int* __restrict__ csr_src,
    const float* __restrict__ ex, const __half* __restrict__ h2,
    const float* __restrict__ bias, void* __restrict__ out_v,
    unsigned* __restrict__ smaxu)
{
    constexpr int NCH = H * C / 4;
    constexpr int HC  = H * C;
    long idx = (long)blockIdx.x * blockDim.x + threadIdx.x;
    if (idx < MAXH) smaxu[idx] = 0u;
    if (idx >= (long)NNODES * NCH) return;
    int n = (int)(idx / NCH);
    int q = (int)(idx - (long)n * NCH);
    int head = q / (C / 4);

    int beg = __ldg(rowptr + n);
    int end = __ldg(rowptr + n + 1);
    float4 acc = make_float4(0.f, 0.f, 0.f, 0.f);
    float zs = 0.f;

    auto accum = [&](int j) {
        int s0 = __ldg(csr_src + j);
        float a0 = __ldg(ex + (long)j * H + head);
        uint2 raw = *(const uint2*)(h2 + (long)s0 * HC + q * 4);
        float2 f0 = __half22float2(*reinterpret_cast<__half2*>(&raw.x));
        float2 f1 = __half22float2(*reinterpret_cast<__half2*>(&raw.y));
        acc.x += f0.x * a0; acc.y += f0.y * a0;
        acc.z += f1.x * a0; acc.w += f1.y * a0;
        zs += a0;
    };

    int j = beg;
    for (; j + 1 < end; j += 2) { accum(j); accum(j + 1); }
    if (j < end) accum(j);

    float rzv = __frcp_rn(zs);
    const float4 bv = __ldg((const float4*)(bias + q * 4));
    float ox = fmaxf(acc.x * rzv + bv.x, 0.f);
    float oy = fmaxf(acc.y * rzv + bv.y, 0.f);
    float oz = fmaxf(acc.z * rzv + bv.z, 0.f);
    float ow = fmaxf(acc.w * rzv + bv.w, 0.f);

    if (HALF_OUT) {
        __half* o = (__half*)out_v;
        __half2 p0 = __floats2half2_rn(ox, oy);
        __half2 p1 = __floats2half2_rn(oz, ow);
        uint2 pk;
        pk.x = *reinterpret_cast<unsigned*>(&p0);
        pk.y = *reinterpret_cast<unsigned*>(&p1);
        *(uint2*)(o + (long)n * HC + q * 4) = pk;
    } else {
        float* o = (float*)out_v;
        *(float4*)(o + (long)n * HC + q * 4) = make_float4(ox, oy, oz, ow);
    }
}

// ================= per-layer templated driver (minus GEMM) =================
template<int H, int C, bool HALF_OUT>
static void run_layer_rest(const float* a_s, const float* a_d, const float* bias,
                           const int* ei, const int* epos,
                           const __half* h2, float* as, float* ad,
                           float* ebuf, unsigned* smaxu,
                           const int* rowptr, const int* csr_src,
                           void* outb)
{
    constexpr int HC = H * C;
    {
        int n = NNODES * H;
        alpha_kernel<H, C><<<(n + 255) / 256, 256>>>(h2, a_s, a_d, as, ad, smaxu);
    }
    {
        int n = ETOT * H;
        edge_fused<H><<<(n + 255) / 256, 256>>>(ei, epos, as, ad, smaxu, ebuf);
    }
    {
        long total = (long)NNODES * (HC / 4);
        int blocks = (int)((total + 255) / 256);
        node_gather<H, C, HALF_OUT><<<blocks, 256>>>(rowptr, csr_src, ebuf, h2, bias, outb, smaxu);
    }
}

template<int K, int N>
static void launch_gemm(const __half* A, const __half* Wt, __half* out2) {
    dim3 grid((N + 63) / 64, (NNODES + 127) / 128);
    gemm_fp16_kernel<K, N><<<grid, 256>>>(A, Wt, out2, NNODES);
}

// ================= host orchestration =================
extern "C" void kernel_launch(void* const* d_in, const int* in_sizes, int n_in,
                              void* d_out, int out_size)
{
    const float* x  = (const float*)d_in[0];
    const int*   ei = (const int*)d_in[1];

    float *as, *ad, *ebuf;
    __half *h2, *xh, *bufh0, *bufh1, *wt;
    unsigned* smaxu;
    int *rowptr, *cnt, *fill, *csr_src, *epos, *bsum;
    {
        void* p;
        cudaGetSymbolAddress(&p, g_h2);      h2      = (__half*)p;
        cudaGetSymbolAddress(&p, g_xh);      xh      = (__half*)p;
        cudaGetSymbolAddress(&p, g_bufh0);   bufh0   = (__half*)p;
        cudaGetSymbolAddress(&p, g_bufh1);   bufh1   = (__half*)p;
        cudaGetSymbolAddress(&p, g_wt);      wt      = (__half*)p;
        cudaGetSymbolAddress(&p, g_as);      as      = (float*)p;
        cudaGetSymbolAddress(&p, g_ad);      ad      = (float*)p;
        cudaGetSymbolAddress(&p, g_e);       ebuf    = (float*)p;
        cudaGetSymbolAddress(&p, g_smaxu);   smaxu   = (unsigned*)p;
        cudaGetSymbolAddress(&p, g_rowptr);  rowptr  = (int*)p;
        cudaGetSymbolAddress(&p, g_cnt);     cnt     = (int*)p;
        cudaGetSymbolAddress(&p, g_fill);    fill    = (int*)p;
        cudaGetSymbolAddress(&p, g_csr_src); csr_src = (int*)p;
        cudaGetSymbolAddress(&p, g_epos);    epos    = (int*)p;
        cudaGetSymbolAddress(&p, g_bsum);    bsum    = (int*)p;
    }

    const float* W[5]; const float* B[5]; const float* AS[5]; const float* AD[5];
    for (int i = 0; i < 5; i++) {
        W[i]  = (const float*)d_in[3 + 4 * i];
        B[i]  = (const float*)d_in[4 + 4 * i];
        AS[i] = (const float*)d_in[5 + 4 * i];
        AD[i] = (const float*)d_in[6 + 4 * i];
    }

    // ---- conversions + CSR build interleaved with layer-0 GEMM ----
    cvt_x_kernel<<<(NNODES * 32 + 255) / 256, 256>>>(x, xh);            // #1
    wt_convert_kernel<<<(WT_TOT + 255) / 256, 256>>>(W[0], W[1], W[2], W[3], W[4], wt); // #2
    csr_zero<<<(NNODES + 255) / 256, 256>>>(cnt, fill, smaxu);          // #3
    launch_gemm< 32, 240>(xh, wt + WT_O0, h2);                          // #4 (profiled)
    csr_hist<<<(ETOT + 255) / 256, 256>>>(ei, cnt);                     // #5
    csr_scan1<<<NSCAN, SCAN_BLK>>>(cnt, rowptr, bsum);                  // #6
    csr_scan2<<<1, 128>>>(bsum);                                        // #7
    csr_scan3<<<NSCAN, SCAN_BLK>>>(rowptr, bsum);                       // #8
    csr_fill<<<(ETOT + 255) / 256, 256>>>(ei, rowptr, fill, csr_src, epos); // #9

    // ---- layer 0 rest (gather applies bias B[0] + relu -> bufh0 fp16) ----
    run_layer_rest<10, 24, true>(AS[0], AD[0], B[0], ei, epos, h2, as, ad, ebuf, smaxu, rowptr, csr_src, bufh0);

    // ---- layers 1-4 ----
    launch_gemm<240, 120>(bufh0, wt + WT_O1, h2);
    run_layer_rest< 5, 24, true>(AS[1], AD[1], B[1], ei, epos, h2, as, ad, ebuf, smaxu, rowptr, csr_src, bufh1);

    launch_gemm<120,  48>(bufh1, wt + WT_O2, h2);
    run_layer_rest< 2, 24, true>(AS[2], AD[2], B[2], ei, epos, h2, as, ad, ebuf, smaxu, rowptr, csr_src, bufh0);

    launch_gemm< 48,  24>(bufh0, wt + WT_O3, h2);
    run_layer_rest< 1, 24, true>(AS[3], AD[3], B[3], ei, epos, h2, as, ad, ebuf, smaxu, rowptr, csr_src, bufh1);

    launch_gemm< 24,  12>(bufh1, wt + WT_O4, h2);
    run_layer_rest< 1, 12, false>(AS[4], AD[4], B[4], ei, epos, h2, as, ad, ebuf, smaxu, rowptr, csr_src, d_out);
}

// round 16
// speedup vs baseline: 1.5578x; 1.0264x over previous
#include <cuda_runtime.h>
#include <cuda_bf16.h>
#include <cuda_fp16.h>

#define NNODES 100000
#define NEDGES 800000
#define ETOT   900000
#define MAXHC  240
#define MAXH   10
#define NEG_SLOPE 0.2f
#define SCAN_BLK 1024
#define NSCAN ((NNODES + SCAN_BLK - 1) / SCAN_BLK)   // 98

// W sizes (transposed fp16): Wt[n*K + k]
#define WT_S0 (32*240)
#define WT_S1 (240*120)
#define WT_S2 (120*48)
#define WT_S3 (48*24)
#define WT_S4 (24*12)
#define WT_O0 0
#define WT_O1 (WT_O0 + WT_S0)
#define WT_O2 (WT_O1 + WT_S1)
#define WT_O3 (WT_O2 + WT_S2)
#define WT_O4 (WT_O3 + WT_S3)
#define WT_TOT (WT_O4 + WT_S4)

// ---------------- scratch (device globals; no allocation allowed) ----------------
__device__ __half   g_h2   [NNODES * MAXHC];    // fp16 h (alpha + gather)
__device__ __half   g_xh   [NNODES * 32];       // fp16 copy of input x
__device__ __half   g_bufh0[NNODES * MAXHC];    // fp16 layer outputs (ping)
__device__ __half   g_bufh1[NNODES * MAXHC];    // fp16 layer outputs (pong)
__device__ __half   g_wt   [WT_TOT];            // fp16 transposed weights
__device__ float    g_as   [NNODES * MAXH];
__device__ float    g_ad   [NNODES * MAXH];
__device__ __half   g_e    [ETOT   * MAXH];     // fp16 per-edge exp values (CSR order)
__device__ unsigned g_smaxu[MAXH];              // per-head global max (encoded)
// CSR (built once per launch)
__device__ int g_rowptr [NNODES + 1];
__device__ int g_cnt    [NNODES];
__device__ int g_fill   [NNODES];
__device__ int g_csr_src[ETOT];
__device__ int g_epos   [ETOT];                 // edge id -> csr position
__device__ int g_bsum   [NSCAN];

// ---------------- helpers ----------------
__device__ __forceinline__ unsigned enc_f(float v) {
    unsigned u = __float_as_uint(v);
    return (u & 0x80000000u) ? ~u : (u | 0x80000000u);
}
__device__ __forceinline__ float dec_f(unsigned u) {
    return __uint_as_float((u & 0x80000000u) ? (u ^ 0x80000000u) : ~u);
}

__device__ __forceinline__ void mma_f16(float* d, const unsigned* a, const unsigned* b) {
    asm volatile("mma.sync.aligned.m16n8k16.row.col.f32.f16.f16.f32 "
        "{%0,%1,%2,%3}, {%4,%5,%6,%7}, {%8,%9}, {%0,%1,%2,%3};"
        : "+f"(d[0]), "+f"(d[1]), "+f"(d[2]), "+f"(d[3])
        : "r"(a[0]), "r"(a[1]), "r"(a[2]), "r"(a[3]), "r"(b[0]), "r"(b[1]));
}

// ================= input conversions (once per launch) =================
__global__ __launch_bounds__(256) void cvt_x_kernel(const float* __restrict__ x,
                                                    __half* __restrict__ xh) {
    int i = blockIdx.x * blockDim.x + threadIdx.x;
    if (i < NNODES * 32) xh[i] = __float2half(x[i]);
}

__global__ __launch_bounds__(256) void wt_convert_kernel(
    const float* __restrict__ W0, const float* __restrict__ W1,
    const float* __restrict__ W2, const float* __restrict__ W3,
    const float* __restrict__ W4, __half* __restrict__ wt)
{
    int i = blockIdx.x * blockDim.x + threadIdx.x;
    if (i >= WT_TOT) return;
    const float* W; int K, N, off;
    if      (i < WT_O1) { W = W0; K = 32;  N = 240; off = WT_O0; }
    else if (i < WT_O2) { W = W1; K = 240; N = 120; off = WT_O1; }
    else if (i < WT_O3) { W = W2; K = 120; N = 48;  off = WT_O2; }
    else if (i < WT_O4) { W = W3; K = 48;  N = 24;  off = WT_O3; }
    else                { W = W4; K = 24;  N = 12;  off = WT_O4; }
    int li = i - off;
    int n = li / K, k = li - n * K;
    wt[i] = __float2half(W[k * N + n]);
}

// ================= CSR build (once per launch) =================
__global__ __launch_bounds__(256) void csr_zero(int* cnt, int* fill, unsigned* smaxu) {
    int i = blockIdx.x * blockDim.x + threadIdx.x;
    if (i < NNODES) { cnt[i] = 0; fill[i] = 0; }
    if (i < MAXH) smaxu[i] = 0u;
}

__global__ __launch_bounds__(256) void csr_hist(const int* __restrict__ ei, int* cnt) {
    int e = blockIdx.x * blockDim.x + threadIdx.x;
    if (e >= ETOT) return;
    int d = (e < NEDGES) ? __ldg(ei + NEDGES + e) : (e - NEDGES);
    atomicAdd(&cnt[d], 1);
}

__global__ __launch_bounds__(SCAN_BLK) void csr_scan1(const int* __restrict__ cnt,
                                                      int* rowptr, int* bsum) {
    __shared__ int sh[SCAN_BLK];
    int gi = blockIdx.x * SCAN_BLK + threadIdx.x;
    int v = (gi < NNODES) ? cnt[gi] : 0;
    sh[threadIdx.x] = v;
    __syncthreads();
    for (int off = 1; off < SCAN_BLK; off <<= 1) {
        int t = (threadIdx.x >= off) ? sh[threadIdx.x - off] : 0;
        __syncthreads();
        sh[threadIdx.x] += t;
        __syncthreads();
    }
    if (gi < NNODES) rowptr[gi] = sh[threadIdx.x] - v;
    if (threadIdx.x == SCAN_BLK - 1) bsum[blockIdx.x] = sh[threadIdx.x];
}

__global__ __launch_bounds__(128) void csr_scan2(int* bsum) {
    __shared__ int sh[128];
    int v = (threadIdx.x < NSCAN) ? bsum[threadIdx.x] : 0;
    sh[threadIdx.x] = v;
    __syncthreads();
    for (int off = 1; off < 128; off <<= 1) {
        int t = (threadIdx.x >= off) ? sh[threadIdx.x - off] : 0;
        __syncthreads();
        sh[threadIdx.x] += t;
        __syncthreads();
    }
    if (threadIdx.x < NSCAN) bsum[threadIdx.x] = sh[threadIdx.x] - v;
}

__global__ __launch_bounds__(SCAN_BLK) void csr_scan3(int* rowptr, const int* __restrict__ bsum) {
    int gi = blockIdx.x * SCAN_BLK + threadIdx.x;
    if (gi < NNODES) rowptr[gi] += bsum[blockIdx.x];
    if (gi == 0) rowptr[NNODES] = ETOT;
}

__global__ __launch_bounds__(256) void csr_fill(const int* __restrict__ ei,
                                                const int* __restrict__ rowptr,
                                                int* fill, int* csr_src, int* epos) {
    int e = blockIdx.x * blockDim.x + threadIdx.x;
    if (e >= ETOT) return;
    int s, d;
    if (e < NEDGES) { s = __ldg(ei + e); d = __ldg(ei + NEDGES + e); }
    else            { s = e - NEDGES; d = s; }
    int pos = rowptr[d] + atomicAdd(&fill[d], 1);
    csr_src[pos] = s;
    epos[e] = pos;
}

// ================= fp16 tensor-core GEMM: out[M,N] = A[M,K] @ Wt[N,K]^T =================
template<int K, int N>
__global__ __launch_bounds__(256, 4) void gemm_fp16_kernel(
    const __half* __restrict__ A, const __half* __restrict__ Wt,
    __half* __restrict__ out2, int M)
{
    __shared__ __half As[2][128][24];
    __shared__ __half Bs[2][64][24];

    const int tid  = threadIdx.x;
    const int lane = tid & 31;
    const int warp = tid >> 5;
    const int wm   = warp & 3;
    const int wn   = warp >> 2;
    const int row0 = blockIdx.y * 128;
    const int col0 = blockIdx.x * 64;

    float acc[2][4][4];
#pragma unroll
    for (int mt = 0; mt < 2; mt++)
#pragma unroll
        for (int nt = 0; nt < 4; nt++)
#pragma unroll
            for (int i = 0; i < 4; i++) acc[mt][nt][i] = 0.f;

    const int arow = tid >> 1;
    const int ako  = (tid & 1) * 8;
    const int gr   = row0 + arow;
    const bool a_ok = (gr < M);
    const __half* a_src = A + (long)(a_ok ? gr : 0) * K + ako;

    const int bn  = tid >> 1;
    const int bko = (tid & 1) * 8;
    const int gn  = col0 + bn;
    const bool b_ok = (tid < 128) && (gn < N);
    const __half* b_src = Wt + (long)(b_ok ? gn : 0) * K + bko;

    auto ldg_a = [&](int k0) -> uint4 {
        if (a_ok && k0 + ako < K) return *(const uint4*)(a_src + k0);
        return make_uint4(0u, 0u, 0u, 0u);
    };
    auto ldg_b = [&](int k0) -> uint4 {
        if (b_ok && k0 + bko < K) return *(const uint4*)(b_src + k0);
        return make_uint4(0u, 0u, 0u, 0u);
    };
    auto store_a = [&](int buf, uint4 v) {
        *(uint4*)&As[buf][arow][ako] = v;
    };
    auto store_b = [&](int buf, uint4 v) {
        if (tid < 128) *(uint4*)&Bs[buf][bn][bko] = v;
    };

    constexpr int NK = (K + 15) / 16;

    store_a(0, ldg_a(0));
    store_b(0, ldg_b(0));
    __syncthreads();

#pragma unroll 1
    for (int s = 0; s < NK; s++) {
        const bool more = (s + 1 < NK);
        uint4 an, bnx;
        if (more) {
            const int k0n = (s + 1) * 16;
            an  = ldg_a(k0n);
            bnx = ldg_b(k0n);
        }

        const int buf = s & 1;
        const int kq = (lane & 3) * 2;
        unsigned af[2][4];
#pragma unroll
        for (int mt = 0; mt < 2; mt++) {
            const int r = wm * 32 + mt * 16 + (lane >> 2);
            af[mt][0] = *(const unsigned*)&As[buf][r][kq];
            af[mt][1] = *(const unsigned*)&As[buf][r + 8][kq];
            af[mt][2] = *(const unsigned*)&As[buf][r][kq + 8];
            af[mt][3] = *(const unsigned*)&As[buf][r + 8][kq + 8];
        }
#pragma unroll
        for (int nt = 0; nt < 4; nt++) {
            const int ci = wn * 32 + nt * 8 + (lane >> 2);
            unsigned bf[2];
            bf[0] = *(const unsigned*)&Bs[buf][ci][kq];
            bf[1] = *(const unsigned*)&Bs[buf][ci][kq + 8];
#pragma unroll
            for (int mt = 0; mt < 2; mt++)
                mma_f16(acc[mt][nt], af[mt], bf);
        }

        if (more) {
            store_a((s + 1) & 1, an);
            store_b((s + 1) & 1, bnx);
            __syncthreads();
        }
    }

#pragma unroll
    for (int mt = 0; mt < 2; mt++) {
#pragma unroll
        for (int nt = 0; nt < 4; nt++) {
            int r = row0 + wm * 32 + mt * 16 + (lane >> 2);
            int c = col0 + wn * 32 + nt * 8 + (lane & 3) * 2;
            if (c + 1 < N) {
                if (r < M)
                    *(__half2*)(out2 + (long)r * N + c) =
                        __floats2half2_rn(acc[mt][nt][0], acc[mt][nt][1]);
                if (r + 8 < M)
                    *(__half2*)(out2 + (long)(r + 8) * N + c) =
                        __floats2half2_rn(acc[mt][nt][2], acc[mt][nt][3]);
            }
        }
    }
}

// ================= alpha (fp16 h) + per-head global max =================
template<int H, int C>
__global__ __launch_bounds__(256) void alpha_kernel(
    const __half* __restrict__ h2, const float* __restrict__ a_s,
    const float* __restrict__ a_d, float* __restrict__ alpha_s,
    float* __restrict__ alpha_d, unsigned* __restrict__ smaxu)
{
    __shared__ unsigned s_max[H];
    if (threadIdx.x < H) s_max[threadIdx.x] = 0u;
    __syncthreads();

    int idx = blockIdx.x * blockDim.x + threadIdx.x;
    if (idx < NNODES * H) {
        int node = idx / H;
        int hh = idx - node * H;
        const uint2* hp   = (const uint2*)(h2 + (long)node * H * C + hh * C);
        const float4* asp = (const float4*)(a_s + hh * C);
        const float4* adp = (const float4*)(a_d + hh * C);
        float ss = 0.f, sd = 0.f;
#pragma unroll
        for (int c = 0; c < C / 4; c++) {
            uint2 raw = __ldg(hp + c);
            float2 f0 = __half22float2(*reinterpret_cast<__half2*>(&raw.x));
            float2 f1 = __half22float2(*reinterpret_cast<__half2*>(&raw.y));
            float4 s4 = __ldg(asp + c);
            float4 d4 = __ldg(adp + c);
            ss += f0.x * s4.x + f0.y * s4.y + f1.x * s4.z + f1.y * s4.w;
            sd += f0.x * d4.x + f0.y * d4.y + f1.x * d4.z + f1.y * d4.w;
        }
        alpha_s[idx] = ss;
        alpha_d[idx] = sd;
        atomicMax(&s_max[hh], enc_f(ss));
    }
    __syncthreads();
    if (threadIdx.x < H)
        atomicMax(&smaxu[threadIdx.x], s_max[threadIdx.x]);
}

// ================= fused edge pass: exp(e - m_ub), fp16 CSR-ordered store =================
template<int H>
__global__ __launch_bounds__(256) void edge_fused(
    const int* __restrict__ ei, const int* __restrict__ epos,
    const float* __restrict__ as, const float* __restrict__ ad,
    const unsigned* __restrict__ smaxu, __half* __restrict__ ebuf)
{
    int idx = blockIdx.x * blockDim.x + threadIdx.x;
    if (idx >= ETOT * H) return;
    int e  = idx / H;
    int hh = idx - e * H;
    int s, d;
    if (e < NEDGES) { s = __ldg(ei + e); d = __ldg(ei + NEDGES + e); }
    else            { s = e - NEDGES; d = s; }
    float asv = __ldg(as + s * H + hh);
    float adv = __ldg(ad + d * H + hh);
    float ev = asv + adv;
    ev = (ev > 0.f) ? ev : NEG_SLOPE * ev;
    float mb = dec_f(__ldg(smaxu + hh)) + adv;
    mb = (mb > 0.f) ? mb : NEG_SLOPE * mb;
    float ex = __expf(ev - mb);
    int pos = __ldg(epos + e);
    ebuf[(long)pos * H + hh] = __float2half(ex);   // scattered 2B write
}

// ================= CSR gather (fp16 h + fp16 ex) + bias + ReLU =================
template<int H, int C, bool HALF_OUT>
__global__ __launch_bounds__(256) void node_gather(
    const int* __restrict__ rowptr, const int* __restrict__ csr_src,
    const __half* __restrict__ ex, const __half* __restrict__ h2,
    const float* __restrict__ bias, void* __restrict__ out_v,
    unsigned* __restrict__ smaxu)
{
    constexpr int NCH = H * C / 4;
    constexpr int HC  = H * C;
    long idx = (long)blockIdx.x * blockDim.x + threadIdx.x;
    if (idx < MAXH) smaxu[idx] = 0u;
    if (idx >= (long)NNODES * NCH) return;
    int n = (int)(idx / NCH);
    int q = (int)(idx - (long)n * NCH);
    int head = q / (C / 4);

    int beg = __ldg(rowptr + n);
    int end = __ldg(rowptr + n + 1);
    float4 acc = make_float4(0.f, 0.f, 0.f, 0.f);
    float zs = 0.f;

    auto accum = [&](int j) {
        int s0 = __ldg(csr_src + j);
        float a0 = __half2float(__ldg(ex + (long)j * H + head));
        uint2 raw = *(const uint2*)(h2 + (long)s0 * HC + q * 4);
        float2 f0 = __half22float2(*reinterpret_cast<__half2*>(&raw.x));
        float2 f1 = __half22float2(*reinterpret_cast<__half2*>(&raw.y));
        acc.x += f0.x * a0; acc.y += f0.y * a0;
        acc.z += f1.x * a0; acc.w += f1.y * a0;
        zs += a0;
    };

    int j = beg;
    for (; j + 3 < end; j += 4) { accum(j); accum(j + 1); accum(j + 2); accum(j + 3); }
    for (; j < end; j++) accum(j);

    float rzv = __frcp_rn(zs);
    const float4 bv = __ldg((const float4*)(bias + q * 4));
    float ox = fmaxf(acc.x * rzv + bv.x, 0.f);
    float oy = fmaxf(acc.y * rzv + bv.y, 0.f);
    float oz = fmaxf(acc.z * rzv + bv.z, 0.f);
    float ow = fmaxf(acc.w * rzv + bv.w, 0.f);

    if (HALF_OUT) {
        __half* o = (__half*)out_v;
        __half2 p0 = __floats2half2_rn(ox, oy);
        __half2 p1 = __floats2half2_rn(oz, ow);
        uint2 pk;
        pk.x = *reinterpret_cast<unsigned*>(&p0);
        pk.y = *reinterpret_cast<unsigned*>(&p1);
        *(uint2*)(o + (long)n * HC + q * 4) = pk;
    } else {
        float* o = (float*)out_v;
        *(float4*)(o + (long)n * HC + q * 4) = make_float4(ox, oy, oz, ow);
    }
}

// ================= per-layer templated driver (minus GEMM) =================
template<int H, int C, bool HALF_OUT>
static void run_layer_rest(const float* a_s, const float* a_d, const float* bias,
                           const int* ei, const int* epos,
                           const __half* h2, float* as, float* ad,
                           __half* ebuf, unsigned* smaxu,
                           const int* rowptr, const int* csr_src,
                           void* outb)
{
    constexpr int HC = H * C;
    {
        int n = NNODES * H;
        alpha_kernel<H, C><<<(n + 255) / 256, 256>>>(h2, a_s, a_d, as, ad, smaxu);
    }
    {
        int n = ETOT * H;
        edge_fused<H><<<(n + 255) / 256, 256>>>(ei, epos, as, ad, smaxu, ebuf);
    }
    {
        long total = (long)NNODES * (HC / 4);
        int blocks = (int)((total + 255) / 256);
        node_gather<H, C, HALF_OUT><<<blocks, 256>>>(rowptr, csr_src, ebuf, h2, bias, outb, smaxu);
    }
}

template<int K, int N>
static void launch_gemm(const __half* A, const __half* Wt, __half* out2) {
    dim3 grid((N + 63) / 64, (NNODES + 127) / 128);
    gemm_fp16_kernel<K, N><<<grid, 256>>>(A, Wt, out2, NNODES);
}

// ================= host orchestration =================
extern "C" void kernel_launch(void* const* d_in, const int* in_sizes, int n_in,
                              void* d_out, int out_size)
{
    const float* x  = (const float*)d_in[0];
    const int*   ei = (const int*)d_in[1];

    float *as, *ad;
    __half *h2, *xh, *bufh0, *bufh1, *wt, *ebuf;
    unsigned* smaxu;
    int *rowptr, *cnt, *fill, *csr_src, *epos, *bsum;
    {
        void* p;
        cudaGetSymbolAddress(&p, g_h2);      h2      = (__half*)p;
        cudaGetSymbolAddress(&p, g_xh);      xh      = (__half*)p;
        cudaGetSymbolAddress(&p, g_bufh0);   bufh0   = (__half*)p;
        cudaGetSymbolAddress(&p, g_bufh1);   bufh1   = (__half*)p;
        cudaGetSymbolAddress(&p, g_wt);      wt      = (__half*)p;
        cudaGetSymbolAddress(&p, g_as);      as      = (float*)p;
        cudaGetSymbolAddress(&p, g_ad);      ad      = (float*)p;
        cudaGetSymbolAddress(&p, g_e);       ebuf    = (__half*)p;
        cudaGetSymbolAddress(&p, g_smaxu);   smaxu   = (unsigned*)p;
        cudaGetSymbolAddress(&p, g_rowptr);  rowptr  = (int*)p;
        cudaGetSymbolAddress(&p, g_cnt);     cnt     = (int*)p;
        cudaGetSymbolAddress(&p, g_fill);    fill    = (int*)p;
        cudaGetSymbolAddress(&p, g_csr_src); csr_src = (int*)p;
        cudaGetSymbolAddress(&p, g_epos);    epos    = (int*)p;
        cudaGetSymbolAddress(&p, g_bsum);    bsum    = (int*)p;
    }

    const float* W[5]; const float* B[5]; const float* AS[5]; const float* AD[5];
    for (int i = 0; i < 5; i++) {
        W[i]  = (const float*)d_in[3 + 4 * i];
        B[i]  = (const float*)d_in[4 + 4 * i];
        AS[i] = (const float*)d_in[5 + 4 * i];
        AD[i] = (const float*)d_in[6 + 4 * i];
    }

    // ---- conversions + CSR build interleaved with layer-0 GEMM ----
    cvt_x_kernel<<<(NNODES * 32 + 255) / 256, 256>>>(x, xh);            // #1
    wt_convert_kernel<<<(WT_TOT + 255) / 256, 256>>>(W[0], W[1], W[2], W[3], W[4], wt); // #2
    csr_zero<<<(NNODES + 255) / 256, 256>>>(cnt, fill, smaxu);          // #3
    launch_gemm< 32, 240>(xh, wt + WT_O0, h2);                          // #4 (profiled)
    csr_hist<<<(ETOT + 255) / 256, 256>>>(ei, cnt);                     // #5
    csr_scan1<<<NSCAN, SCAN_BLK>>>(cnt, rowptr, bsum);                  // #6
    csr_scan2<<<1, 128>>>(bsum);                                        // #7
    csr_scan3<<<NSCAN, SCAN_BLK>>>(rowptr, bsum);                       // #8
    csr_fill<<<(ETOT + 255) / 256, 256>>>(ei, rowptr, fill, csr_src, epos); // #9

    // ---- layer 0 rest ----
    run_layer_rest<10, 24, true>(AS[0], AD[0], B[0], ei, epos, h2, as, ad, ebuf, smaxu, rowptr, csr_src, bufh0);

    // ---- layers 1-4 ----
    launch_gemm<240, 120>(bufh0, wt + WT_O1, h2);
    run_layer_rest< 5, 24, true>(AS[1], AD[1], B[1], ei, epos, h2, as, ad, ebuf, smaxu, rowptr, csr_src, bufh1);

    launch_gemm<120,  48>(bufh1, wt + WT_O2, h2);
    run_layer_rest< 2, 24, true>(AS[2], AD[2], B[2], ei, epos, h2, as, ad, ebuf, smaxu, rowptr, csr_src, bufh0);

    launch_gemm< 48,  24>(bufh0, wt + WT_O3, h2);
    run_layer_rest< 1, 24, true>(AS[3], AD[3], B[3], ei, epos, h2, as, ad, ebuf, smaxu, rowptr, csr_src, bufh1);

    launch_gemm< 24,  12>(bufh1, wt + WT_O4, h2);
    run_layer_rest< 1, 12, false>(AS[4], AD[4], B[4], ei, epos, h2, as, ad, ebuf, smaxu, rowptr, csr_src, d_out);
}

// round 17
// speedup vs baseline: 1.9158x; 1.2298x over previous
#include <cuda_runtime.h>
#include <cuda_bf16.h>
#include <cuda_fp16.h>

#define NNODES 100000
#define NEDGES 800000
#define ETOT   900000
#define MAXHC  240
#define MAXH   10
#define NEG_SLOPE 0.2f
#define SCAN_BLK 1024
#define NSCAN ((NNODES + SCAN_BLK - 1) / SCAN_BLK)   // 98

// W sizes (transposed fp16): Wt[n*K + k]
#define WT_S0 (32*240)
#define WT_S1 (240*120)
#define WT_S2 (120*48)
#define WT_S3 (48*24)
#define WT_S4 (24*12)
#define WT_O0 0
#define WT_O1 (WT_O0 + WT_S0)
#define WT_O2 (WT_O1 + WT_S1)
#define WT_O3 (WT_O2 + WT_S2)
#define WT_O4 (WT_O3 + WT_S3)
#define WT_TOT (WT_O4 + WT_S4)

// ---------------- scratch (device globals; no allocation allowed) ----------------
__device__ __half   g_h2   [NNODES * MAXHC];    // fp16 h (alpha + gather)
__device__ __half   g_xh   [NNODES * 32];       // fp16 copy of input x
__device__ __half   g_bufh0[NNODES * MAXHC];    // fp16 layer outputs (ping)
__device__ __half   g_bufh1[NNODES * MAXHC];    // fp16 layer outputs (pong)
__device__ __half   g_wt   [WT_TOT];            // fp16 transposed weights
__device__ float    g_as   [NNODES * MAXH];
__device__ float    g_ad   [NNODES * MAXH];
__device__ unsigned g_smaxu[MAXH];              // per-head global max (encoded)
// CSR (built once per launch)
__device__ int g_rowptr [NNODES + 1];
__device__ int g_cnt    [NNODES];
__device__ int g_fill   [NNODES];
__device__ int g_csr_src[ETOT];
__device__ int g_bsum   [NSCAN];

// ---------------- helpers ----------------
__device__ __forceinline__ unsigned enc_f(float v) {
    unsigned u = __float_as_uint(v);
    return (u & 0x80000000u) ? ~u : (u | 0x80000000u);
}
__device__ __forceinline__ float dec_f(unsigned u) {
    return __uint_as_float((u & 0x80000000u) ? (u ^ 0x80000000u) : ~u);
}

__device__ __forceinline__ void mma_f16(float* d, const unsigned* a, const unsigned* b) {
    asm volatile("mma.sync.aligned.m16n8k16.row.col.f32.f16.f16.f32 "
        "{%0,%1,%2,%3}, {%4,%5,%6,%7}, {%8,%9}, {%0,%1,%2,%3};"
        : "+f"(d[0]), "+f"(d[1]), "+f"(d[2]), "+f"(d[3])
        : "r"(a[0]), "r"(a[1]), "r"(a[2]), "r"(a[3]), "r"(b[0]), "r"(b[1]));
}

// ================= input conversions (once per launch) =================
__global__ __launch_bounds__(256) void cvt_x_kernel(const float* __restrict__ x,
                                                    __half* __restrict__ xh) {
    int i = blockIdx.x * blockDim.x + threadIdx.x;
    if (i < NNODES * 32) xh[i] = __float2half(x[i]);
}

__global__ __launch_bounds__(256) void wt_convert_kernel(
    const float* __restrict__ W0, const float* __restrict__ W1,
    const float* __restrict__ W2, const float* __restrict__ W3,
    const float* __restrict__ W4, __half* __restrict__ wt)
{
    int i = blockIdx.x * blockDim.x + threadIdx.x;
    if (i >= WT_TOT) return;
    const float* W; int K, N, off;
    if      (i < WT_O1) { W = W0; K = 32;  N = 240; off = WT_O0; }
    else if (i < WT_O2) { W = W1; K = 240; N = 120; off = WT_O1; }
    else if (i < WT_O3) { W = W2; K = 120; N = 48;  off = WT_O2; }
    else if (i < WT_O4) { W = W3; K = 48;  N = 24;  off = WT_O3; }
    else                { W = W4; K = 24;  N = 12;  off = WT_O4; }
    int li = i - off;
    int n = li / K, k = li - n * K;
    wt[i] = __float2half(W[k * N + n]);
}

// ================= CSR build (once per launch) =================
__global__ __launch_bounds__(256) void csr_zero(int* cnt, int* fill, unsigned* smaxu) {
    int i = blockIdx.x * blockDim.x + threadIdx.x;
    if (i < NNODES) { cnt[i] = 0; fill[i] = 0; }
    if (i < MAXH) smaxu[i] = 0u;
}

__global__ __launch_bounds__(256) void csr_hist(const int* __restrict__ ei, int* cnt) {
    int e = blockIdx.x * blockDim.x + threadIdx.x;
    if (e >= ETOT) return;
    int d = (e < NEDGES) ? __ldg(ei + NEDGES + e) : (e - NEDGES);
    atomicAdd(&cnt[d], 1);
}

__global__ __launch_bounds__(SCAN_BLK) void csr_scan1(const int* __restrict__ cnt,
                                                      int* rowptr, int* bsum) {
    __shared__ int sh[SCAN_BLK];
    int gi = blockIdx.x * SCAN_BLK + threadIdx.x;
    int v = (gi < NNODES) ? cnt[gi] : 0;
    sh[threadIdx.x] = v;
    __syncthreads();
    for (int off = 1; off < SCAN_BLK; off <<= 1) {
        int t = (threadIdx.x >= off) ? sh[threadIdx.x - off] : 0;
        __syncthreads();
        sh[threadIdx.x] += t;
        __syncthreads();
    }
    if (gi < NNODES) rowptr[gi] = sh[threadIdx.x] - v;
    if (threadIdx.x == SCAN_BLK - 1) bsum[blockIdx.x] = sh[threadIdx.x];
}

__global__ __launch_bounds__(128) void csr_scan2(int* bsum) {
    __shared__ int sh[128];
    int v = (threadIdx.x < NSCAN) ? bsum[threadIdx.x] : 0;
    sh[threadIdx.x] = v;
    __syncthreads();
    for (int off = 1; off < 128; off <<= 1) {
        int t = (threadIdx.x >= off) ? sh[threadIdx.x - off] : 0;
        __syncthreads();
        sh[threadIdx.x] += t;
        __syncthreads();
    }
    if (threadIdx.x < NSCAN) bsum[threadIdx.x] = sh[threadIdx.x] - v;
}

__global__ __launch_bounds__(SCAN_BLK) void csr_scan3(int* rowptr, const int* __restrict__ bsum) {
    int gi = blockIdx.x * SCAN_BLK + threadIdx.x;
    if (gi < NNODES) rowptr[gi] += bsum[blockIdx.x];
    if (gi == 0) rowptr[NNODES] = ETOT;
}

__global__ __launch_bounds__(256) void csr_fill(const int* __restrict__ ei,
                                                const int* __restrict__ rowptr,
                                                int* fill, int* csr_src) {
    int e = blockIdx.x * blockDim.x + threadIdx.x;
    if (e >= ETOT) return;
    int s, d;
    if (e < NEDGES) { s = __ldg(ei + e); d = __ldg(ei + NEDGES + e); }
    else            { s = e - NEDGES; d = s; }
    int pos = rowptr[d] + atomicAdd(&fill[d], 1);
    csr_src[pos] = s;
}

// ================= fp16 tensor-core GEMM: out[M,N] = A[M,K] @ Wt[N,K]^T =================
// Also resets smaxu for the following alpha pass (safe: gather that READS smaxu
// completed before this kernel launches; alpha that WRITES it launches after).
template<int K, int N>
__global__ __launch_bounds__(256, 4) void gemm_fp16_kernel(
    const __half* __restrict__ A, const __half* __restrict__ Wt,
    __half* __restrict__ out2, unsigned* __restrict__ smaxu, int M)
{
    __shared__ __half As[2][128][24];
    __shared__ __half Bs[2][64][24];

    const int tid  = threadIdx.x;
    if (blockIdx.x == 0 && blockIdx.y == 0 && tid < MAXH) smaxu[tid] = 0u;

    const int lane = tid & 31;
    const int warp = tid >> 5;
    const int wm   = warp & 3;
    const int wn   = warp >> 2;
    const int row0 = blockIdx.y * 128;
    const int col0 = blockIdx.x * 64;

    float acc[2][4][4];
#pragma unroll
    for (int mt = 0; mt < 2; mt++)
#pragma unroll
        for (int nt = 0; nt < 4; nt++)
#pragma unroll
            for (int i = 0; i < 4; i++) acc[mt][nt][i] = 0.f;

    const int arow = tid >> 1;
    const int ako  = (tid & 1) * 8;
    const int gr   = row0 + arow;
    const bool a_ok = (gr < M);
    const __half* a_src = A + (long)(a_ok ? gr : 0) * K + ako;

    const int bn  = tid >> 1;
    const int bko = (tid & 1) * 8;
    const int gn  = col0 + bn;
    const bool b_ok = (tid < 128) && (gn < N);
    const __half* b_src = Wt + (long)(b_ok ? gn : 0) * K + bko;

    auto ldg_a = [&](int k0) -> uint4 {
        if (a_ok && k0 + ako < K) return *(const uint4*)(a_src + k0);
        return make_uint4(0u, 0u, 0u, 0u);
    };
    auto ldg_b = [&](int k0) -> uint4 {
        if (b_ok && k0 + bko < K) return *(const uint4*)(b_src + k0);
        return make_uint4(0u, 0u, 0u, 0u);
    };
    auto store_a = [&](int buf, uint4 v) {
        *(uint4*)&As[buf][arow][ako] = v;
    };
    auto store_b = [&](int buf, uint4 v) {
        if (tid < 128) *(uint4*)&Bs[buf][bn][bko] = v;
    };

    constexpr int NK = (K + 15) / 16;

    store_a(0, ldg_a(0));
    store_b(0, ldg_b(0));
    __syncthreads();

#pragma unroll 1
    for (int s = 0; s < NK; s++) {
        const bool more = (s + 1 < NK);
        uint4 an, bnx;
        if (more) {
            const int k0n = (s + 1) * 16;
            an  = ldg_a(k0n);
            bnx = ldg_b(k0n);
        }

        const int buf = s & 1;
        const int kq = (lane & 3) * 2;
        unsigned af[2][4];
#pragma unroll
        for (int mt = 0; mt < 2; mt++) {
            const int r = wm * 32 + mt * 16 + (lane >> 2);
            af[mt][0] = *(const unsigned*)&As[buf][r][kq];
            af[mt][1] = *(const unsigned*)&As[buf][r + 8][kq];
            af[mt][2] = *(const unsigned*)&As[buf][r][kq + 8];
            af[mt][3] = *(const unsigned*)&As[buf][r + 8][kq + 8];
        }
#pragma unroll
        for (int nt = 0; nt < 4; nt++) {
            const int ci = wn * 32 + nt * 8 + (lane >> 2);
            unsigned bf[2];
            bf[0] = *(const unsigned*)&Bs[buf][ci][kq];
            bf[1] = *(const unsigned*)&Bs[buf][ci][kq + 8];
#pragma unroll
            for (int mt = 0; mt < 2; mt++)
                mma_f16(acc[mt][nt], af[mt], bf);
        }

        if (more) {
            store_a((s + 1) & 1, an);
            store_b((s + 1) & 1, bnx);
            __syncthreads();
        }
    }

#pragma unroll
    for (int mt = 0; mt < 2; mt++) {
#pragma unroll
        for (int nt = 0; nt < 4; nt++) {
            int r = row0 + wm * 32 + mt * 16 + (lane >> 2);
            int c = col0 + wn * 32 + nt * 8 + (lane & 3) * 2;
            if (c + 1 < N) {
                if (r < M)
                    *(__half2*)(out2 + (long)r * N + c) =
                        __floats2half2_rn(acc[mt][nt][0], acc[mt][nt][1]);
                if (r + 8 < M)
                    *(__half2*)(out2 + (long)(r + 8) * N + c) =
                        __floats2half2_rn(acc[mt][nt][2], acc[mt][nt][3]);
            }
        }
    }
}

// ================= alpha (fp16 h) + per-head global max =================
template<int H, int C>
__global__ __launch_bounds__(256) void alpha_kernel(
    const __half* __restrict__ h2, const float* __restrict__ a_s,
    const float* __restrict__ a_d, float* __restrict__ alpha_s,
    float* __restrict__ alpha_d, unsigned* __restrict__ smaxu)
{
    __shared__ unsigned s_max[H];
    if (threadIdx.x < H) s_max[threadIdx.x] = 0u;
    __syncthreads();

    int idx = blockIdx.x * blockDim.x + threadIdx.x;
    if (idx < NNODES * H) {
        int node = idx / H;
        int hh = idx - node * H;
        const uint2* hp   = (const uint2*)(h2 + (long)node * H * C + hh * C);
        const float4* asp = (const float4*)(a_s + hh * C);
        const float4* adp = (const float4*)(a_d + hh * C);
        float ss = 0.f, sd = 0.f;
#pragma unroll
        for (int c = 0; c < C / 4; c++) {
            uint2 raw = __ldg(hp + c);
            float2 f0 = __half22float2(*reinterpret_cast<__half2*>(&raw.x));
            float2 f1 = __half22float2(*reinterpret_cast<__half2*>(&raw.y));
            float4 s4 = __ldg(asp + c);
            float4 d4 = __ldg(adp + c);
            ss += f0.x * s4.x + f0.y * s4.y + f1.x * s4.z + f1.y * s4.w;
            sd += f0.x * d4.x + f0.y * d4.y + f1.x * d4.z + f1.y * d4.w;
        }
        alpha_s[idx] = ss;
        alpha_d[idx] = sd;
        atomicMax(&s_max[hh], enc_f(ss));
    }
    __syncthreads();
    if (threadIdx.x < H)
        atomicMax(&smaxu[threadIdx.x], s_max[threadIdx.x]);
}

// ================= fused softmax + CSR gather + bias + ReLU =================
// For each (node, 4-chunk): recompute ex = exp(lrelu(as[s]+ad[n]) - m_ub) inline,
// accumulate ex*h[src] and ex, normalize, add bias, relu.
template<int H, int C, bool HALF_OUT>
__global__ __launch_bounds__(256) void node_gather(
    const int* __restrict__ rowptr, const int* __restrict__ csr_src,
    const float* __restrict__ as, const float* __restrict__ ad,
    const unsigned* __restrict__ smaxu, const __half* __restrict__ h2,
    const float* __restrict__ bias, void* __restrict__ out_v)
{
    constexpr int NCH = H * C / 4;
    constexpr int HC  = H * C;
    long idx = (long)blockIdx.x * blockDim.x + threadIdx.x;
    if (idx >= (long)NNODES * NCH) return;
    int n = (int)(idx / NCH);
    int q = (int)(idx - (long)n * NCH);
    int head = q / (C / 4);

    float adv = __ldg(ad + (long)n * H + head);
    float mb  = dec_f(__ldg(smaxu + head)) + adv;
    mb = (mb > 0.f) ? mb : NEG_SLOPE * mb;

    int beg = __ldg(rowptr + n);
    int end = __ldg(rowptr + n + 1);
    float4 acc = make_float4(0.f, 0.f, 0.f, 0.f);
    float zs = 0.f;

    auto accum = [&](int j) {
        int s0 = __ldg(csr_src + j);
        float asv = __ldg(as + (long)s0 * H + head);
        float ev = asv + adv;
        ev = (ev > 0.f) ? ev : NEG_SLOPE * ev;
        float exv = __expf(ev - mb);
        uint2 raw = *(const uint2*)(h2 + (long)s0 * HC + q * 4);
        float2 f0 = __half22float2(*reinterpret_cast<__half2*>(&raw.x));
        float2 f1 = __half22float2(*reinterpret_cast<__half2*>(&raw.y));
        acc.x += f0.x * exv; acc.y += f0.y * exv;
        acc.z += f1.x * exv; acc.w += f1.y * exv;
        zs += exv;
    };

    int j = beg;
    for (; j + 3 < end; j += 4) { accum(j); accum(j + 1); accum(j + 2); accum(j + 3); }
    for (; j < end; j++) accum(j);

    float rzv = __frcp_rn(zs);
    const float4 bv = __ldg((const float4*)(bias + q * 4));
    float ox = fmaxf(acc.x * rzv + bv.x, 0.f);
    float oy = fmaxf(acc.y * rzv + bv.y, 0.f);
    float oz = fmaxf(acc.z * rzv + bv.z, 0.f);
    float ow = fmaxf(acc.w * rzv + bv.w, 0.f);

    if (HALF_OUT) {
        __half* o = (__half*)out_v;
        __half2 p0 = __floats2half2_rn(ox, oy);
        __half2 p1 = __floats2half2_rn(oz, ow);
        uint2 pk;
        pk.x = *reinterpret_cast<unsigned*>(&p0);
        pk.y = *reinterpret_cast<unsigned*>(&p1);
        *(uint2*)(o + (long)n * HC + q * 4) = pk;
    } else {
        float* o = (float*)out_v;
        *(float4*)(o + (long)n * HC + q * 4) = make_float4(ox, oy, oz, ow);
    }
}

// ================= per-layer templated driver (minus GEMM) =================
template<int H, int C, bool HALF_OUT>
static void run_layer_rest(const float* a_s, const float* a_d, const float* bias,
                           const __half* h2, float* as, float* ad,
                           unsigned* smaxu,
                           const int* rowptr, const int* csr_src,
                           void* outb)
{
    constexpr int HC = H * C;
    {
        int n = NNODES * H;
        alpha_kernel<H, C><<<(n + 255) / 256, 256>>>(h2, a_s, a_d, as, ad, smaxu);
    }
    {
        long total = (long)NNODES * (HC / 4);
        int blocks = (int)((total + 255) / 256);
        node_gather<H, C, HALF_OUT><<<blocks, 256>>>(rowptr, csr_src, as, ad, smaxu, h2, bias, outb);
    }
}

template<int K, int N>
static void launch_gemm(const __half* A, const __half* Wt, __half* out2, unsigned* smaxu) {
    dim3 grid((N + 63) / 64, (NNODES + 127) / 128);
    gemm_fp16_kernel<K, N><<<grid, 256>>>(A, Wt, out2, smaxu, NNODES);
}

// ================= host orchestration =================
extern "C" void kernel_launch(void* const* d_in, const int* in_sizes, int n_in,
                              void* d_out, int out_size)
{
    const float* x  = (const float*)d_in[0];
    const int*   ei = (const int*)d_in[1];

    float *as, *ad;
    __half *h2, *xh, *bufh0, *bufh1, *wt;
    unsigned* smaxu;
    int *rowptr, *cnt, *fill, *csr_src, *bsum;
    {
        void* p;
        cudaGetSymbolAddress(&p, g_h2);      h2      = (__half*)p;
        cudaGetSymbolAddress(&p, g_xh);      xh      = (__half*)p;
        cudaGetSymbolAddress(&p, g_bufh0);   bufh0   = (__half*)p;
        cudaGetSymbolAddress(&p, g_bufh1);   bufh1   = (__half*)p;
        cudaGetSymbolAddress(&p, g_wt);      wt      = (__half*)p;
        cudaGetSymbolAddress(&p, g_as);      as      = (float*)p;
        cudaGetSymbolAddress(&p, g_ad);      ad      = (float*)p;
        cudaGetSymbolAddress(&p, g_smaxu);   smaxu   = (unsigned*)p;
        cudaGetSymbolAddress(&p, g_rowptr);  rowptr  = (int*)p;
        cudaGetSymbolAddress(&p, g_cnt);     cnt     = (int*)p;
        cudaGetSymbolAddress(&p, g_fill);    fill    = (int*)p;
        cudaGetSymbolAddress(&p, g_csr_src); csr_src = (int*)p;
        cudaGetSymbolAddress(&p, g_bsum);    bsum    = (int*)p;
    }

    const float* W[5]; const float* B[5]; const float* AS[5]; const float* AD[5];
    for (int i = 0; i < 5; i++) {
        W[i]  = (const float*)d_in[3 + 4 * i];
        B[i]  = (const float*)d_in[4 + 4 * i];
        AS[i] = (const float*)d_in[5 + 4 * i];
        AD[i] = (const float*)d_in[6 + 4 * i];
    }

    // ---- conversions + CSR build interleaved with layer-0 GEMM ----
    cvt_x_kernel<<<(NNODES * 32 + 255) / 256, 256>>>(x, xh);            // #1
    wt_convert_kernel<<<(WT_TOT + 255) / 256, 256>>>(W[0], W[1], W[2], W[3], W[4], wt); // #2
    csr_zero<<<(NNODES + 255) / 256, 256>>>(cnt, fill, smaxu);          // #3
    launch_gemm< 32, 240>(xh, wt + WT_O0, h2, smaxu);                   // #4 (profiled)
    csr_hist<<<(ETOT + 255) / 256, 256>>>(ei, cnt);                     // #5
    csr_scan1<<<NSCAN, SCAN_BLK>>>(cnt, rowptr, bsum);                  // #6
    csr_scan2<<<1, 128>>>(bsum);                                        // #7
    csr_scan3<<<NSCAN, SCAN_BLK>>>(rowptr, bsum);                       // #8
    csr_fill<<<(ETOT + 255) / 256, 256>>>(ei, rowptr, fill, csr_src);   // #9

    // ---- layer 0 rest ----
    run_layer_rest<10, 24, true>(AS[0], AD[0], B[0], h2, as, ad, smaxu, rowptr, csr_src, bufh0);

    // ---- layers 1-4 (each GEMM resets smaxu for the following alpha) ----
    launch_gemm<240, 120>(bufh0, wt + WT_O1, h2, smaxu);
    run_layer_rest< 5, 24, true>(AS[1], AD[1], B[1], h2, as, ad, smaxu, rowptr, csr_src, bufh1);

    launch_gemm<120,  48>(bufh1, wt + WT_O2, h2, smaxu);
    run_layer_rest< 2, 24, true>(AS[2], AD[2], B[2], h2, as, ad, smaxu, rowptr, csr_src, bufh0);

    launch_gemm< 48,  24>(bufh0, wt + WT_O3, h2, smaxu);
    run_layer_rest< 1, 24, true>(AS[3], AD[3], B[3], h2, as, ad, smaxu, rowptr, csr_src, bufh1);

    launch_gemm< 24,  12>(bufh1, wt + WT_O4, h2, smaxu);
    run_layer_rest< 1, 12, false>(AS[4], AD[4], B[4], h2, as, ad, smaxu, rowptr, csr_src, d_out);
}